// round 1
// baseline (speedup 1.0000x reference)
#include <cuda_runtime.h>
#include <math.h>

// Problem constants
constexpr int N   = 8;
constexpr int C   = 128;
constexpr int CW  = 64;
constexpr int CIN = C + CW;   // 192
constexpr int H   = 96;
constexpr int W   = 96;
constexpr int HW  = H * W;    // 9216
constexpr int NB  = 6;        // NUM_BASES
constexpr int TEM = 6;
constexpr int B36 = NB * TEM; // 36
constexpr int L9  = 9;        // KS*KS
constexpr int K768 = C * NB;  // 768

// Static scratch (no allocations allowed)
__device__ float g_hmid [N * C * HW];             // 37.7 MB
__device__ float g_bases[N * NB * L9 * HW];       // 15.9 MB
__device__ float g_bo   [(size_t)N * K768 * HW];  // 226.5 MB

// ---------------------------------------------------------------------------
// Kernel 1: conv1 (3x3, 192->128) + tanh  -> g_hmid
// One block per (n, y). 128 co x 96 x outputs, 256 threads, 8co x 6x per thread.
// ---------------------------------------------------------------------------
__global__ __launch_bounds__(256) void k_conv1(
    const float* __restrict__ feat, const float* __restrict__ wgt,
    const float* __restrict__ w1,   const float* __restrict__ b1)
{
    const int n = blockIdx.z;
    const int y = blockIdx.y;
    const int tid = threadIdx.x;
    const int tx  = tid & 15;      // x group
    const int tco = tid >> 4;      // co group
    const int x0  = tx * 6;
    const int co0 = tco * 8;

    __shared__ float sIn[4 * 3 * 100];   // [ci_l][row][x+1], rows y-1..y+1, x=-1..96
    __shared__ float sW [4 * 9 * 132];   // [ci_l*9+k][co], padded row

    float acc[8][6];
    #pragma unroll
    for (int i = 0; i < 8; i++)
        #pragma unroll
        for (int j = 0; j < 6; j++) acc[i][j] = 0.f;

    for (int cc = 0; cc < CIN; cc += 4) {
        __syncthreads();
        // Load input tile (4 ci x 3 rows x 98 cols, zero-padded)
        for (int i = tid; i < 4 * 3 * 98; i += 256) {
            int cil = i / 294;
            int rem = i - cil * 294;
            int r   = rem / 98;
            int xx  = rem - r * 98;
            int gy  = y + r - 1;
            int gx  = xx - 1;
            float v = 0.f;
            if (gy >= 0 && gy < H && gx >= 0 && gx < W) {
                int ci = cc + cil;
                v = (ci < C) ? feat[((n * C + ci) * H + gy) * W + gx]
                             : wgt [((n * CW + (ci - C)) * H + gy) * W + gx];
            }
            sIn[(cil * 3 + r) * 100 + xx] = v;
        }
        // Load weights: i = co*36 + cil*9 + k  (36 consecutive floats per co)
        for (int i = tid; i < 128 * 36; i += 256) {
            int co  = i / 36;
            int rem = i - co * 36;
            int cil = rem / 9;
            int k   = rem - cil * 9;
            sW[(cil * 9 + k) * 132 + co] = w1[(co * CIN + cc + cil) * 9 + k];
        }
        __syncthreads();

        #pragma unroll
        for (int cil = 0; cil < 4; cil++) {
            #pragma unroll
            for (int ky = 0; ky < 3; ky++) {
                const float* rowp = &sIn[(cil * 3 + ky) * 100];
                #pragma unroll
                for (int kx = 0; kx < 3; kx++) {
                    const int k = ky * 3 + kx;
                    float a[8], b[6];
                    #pragma unroll
                    for (int i = 0; i < 8; i++) a[i] = sW[(cil * 9 + k) * 132 + co0 + i];
                    #pragma unroll
                    for (int j = 0; j < 6; j++) b[j] = rowp[x0 + kx + j];
                    #pragma unroll
                    for (int i = 0; i < 8; i++)
                        #pragma unroll
                        for (int j = 0; j < 6; j++)
                            acc[i][j] = fmaf(a[i], b[j], acc[i][j]);
                }
            }
        }
    }

    #pragma unroll
    for (int i = 0; i < 8; i++) {
        const float bb = b1[co0 + i];
        #pragma unroll
        for (int j = 0; j < 6; j++)
            g_hmid[((n * C + co0 + i) * H + y) * W + x0 + j] = tanhf(acc[i][j] + bb);
    }
}

// ---------------------------------------------------------------------------
// Kernel 2: conv2 (1x1, 128->36) + tanh, then combine with FB bases -> g_bases
// One thread per pixel. W2 transposed in smem, read as float4 broadcasts.
// g_bases layout: [n][m*9+l][hw]
// ---------------------------------------------------------------------------
__global__ __launch_bounds__(256) void k_conv2_bases(
    const float* __restrict__ w2, const float* __restrict__ b2,
    const float* __restrict__ bbuf)
{
    __shared__ float sW2t[128 * 36];  // [ci][ch]
    __shared__ float sBB[54];         // [t][l]
    const int tid = threadIdx.x;

    for (int i = tid; i < 128 * 36; i += 256) {
        int ci = i / 36;
        int ch = i - ci * 36;
        sW2t[i] = w2[ch * 128 + ci];
    }
    if (tid < 54) sBB[tid] = bbuf[tid];
    __syncthreads();

    const int p  = blockIdx.x * 256 + tid;   // [0, N*HW)
    const int n  = p / HW;
    const int hw = p - n * HW;

    float acc[36];
    #pragma unroll
    for (int i = 0; i < 36; i++) acc[i] = 0.f;

    const float* hm = &g_hmid[(size_t)n * C * HW + hw];
    for (int ci = 0; ci < 128; ci++) {
        const float hv = hm[ci * HW];
        const float4* wrow = reinterpret_cast<const float4*>(&sW2t[ci * 36]);
        #pragma unroll
        for (int q = 0; q < 9; q++) {
            float4 w4 = wrow[q];
            acc[q * 4 + 0] = fmaf(w4.x, hv, acc[q * 4 + 0]);
            acc[q * 4 + 1] = fmaf(w4.y, hv, acc[q * 4 + 1]);
            acc[q * 4 + 2] = fmaf(w4.z, hv, acc[q * 4 + 2]);
            acc[q * 4 + 3] = fmaf(w4.w, hv, acc[q * 4 + 3]);
        }
    }

    float bv[36];
    #pragma unroll
    for (int i = 0; i < 36; i++) bv[i] = tanhf(acc[i] + b2[i]);

    #pragma unroll
    for (int m = 0; m < 6; m++) {
        #pragma unroll
        for (int l = 0; l < 9; l++) {
            float s = 0.f;
            #pragma unroll
            for (int t = 0; t < 6; t++) s = fmaf(bv[m * 6 + t], sBB[t * 9 + l], s);
            g_bases[(n * 54 + m * 9 + l) * HW + hw] = s;
        }
    }
}

// ---------------------------------------------------------------------------
// Kernel 3: per-pixel filtering: bases_out[b, c*6+m, hw] = sum_l bases[m,l]*patch[c,l]
// One thread per pixel; bases held in registers across the c-loop.
// ---------------------------------------------------------------------------
__global__ __launch_bounds__(256) void k_bases_out(const float* __restrict__ feat)
{
    const int p  = blockIdx.x * 256 + threadIdx.x;
    const int n  = p / HW;
    const int hw = p - n * HW;
    const int y  = hw / W;
    const int x  = hw - y * W;

    float bs[6][9];
    #pragma unroll
    for (int m = 0; m < 6; m++)
        #pragma unroll
        for (int l = 0; l < 9; l++)
            bs[m][l] = g_bases[(n * 54 + m * 9 + l) * HW + hw];

    const float* fb = &feat[(size_t)n * C * HW];
    float* bo = &g_bo[(size_t)n * K768 * HW + hw];

    for (int c = 0; c < 128; c++) {
        float pv[9];
        #pragma unroll
        for (int l = 0; l < 9; l++) {
            const int gy = y + l / 3 - 1;
            const int gx = x + (l % 3) - 1;
            pv[l] = (gy >= 0 && gy < H && gx >= 0 && gx < W)
                    ? fb[(c * H + gy) * W + gx] : 0.f;
        }
        #pragma unroll
        for (int m = 0; m < 6; m++) {
            float s = 0.f;
            #pragma unroll
            for (int l = 0; l < 9; l++) s = fmaf(bs[m][l], pv[l], s);
            bo[(c * 6 + m) * HW] = s;
        }
    }
}

// ---------------------------------------------------------------------------
// Kernel 4: final 1x1: out[c, p] = sum_k coef[c,k] * bo[k,p] + bias[c]
// SGEMM M=128, K=768, N=9216 per image. 128x128 tile, 8x8 per thread.
// ---------------------------------------------------------------------------
__global__ __launch_bounds__(256) void k_out_gemm(
    const float* __restrict__ coef, const float* __restrict__ bias,
    float* __restrict__ out)
{
    const int n  = blockIdx.z;
    const int p0 = blockIdx.x * 128;
    const int tid = threadIdx.x;
    const int tp = tid & 15;
    const int tc = tid >> 4;
    const int c0  = tc * 8;
    const int pp0 = tp * 8;

    __shared__ float sA[8 * 132];   // [kk][c]
    __shared__ float sB[8 * 132];   // [kk][p]

    float acc[8][8];
    #pragma unroll
    for (int i = 0; i < 8; i++)
        #pragma unroll
        for (int j = 0; j < 8; j++) acc[i][j] = 0.f;

    const float* bo = &g_bo[(size_t)n * K768 * HW + p0];

    for (int k0 = 0; k0 < K768; k0 += 8) {
        __syncthreads();
        for (int i = tid; i < 1024; i += 256) {
            int c  = i >> 3;
            int kk = i & 7;
            sA[kk * 132 + c] = coef[c * K768 + k0 + kk];
        }
        for (int i = tid; i < 1024; i += 256) {
            int kk = i >> 7;
            int pp = i & 127;
            sB[kk * 132 + pp] = bo[(k0 + kk) * HW + pp];
        }
        __syncthreads();
        #pragma unroll
        for (int kk = 0; kk < 8; kk++) {
            float a[8], b[8];
            #pragma unroll
            for (int i = 0; i < 8; i++) a[i] = sA[kk * 132 + c0 + i];
            #pragma unroll
            for (int j = 0; j < 8; j++) b[j] = sB[kk * 132 + pp0 + j];
            #pragma unroll
            for (int i = 0; i < 8; i++)
                #pragma unroll
                for (int j = 0; j < 8; j++)
                    acc[i][j] = fmaf(a[i], b[j], acc[i][j]);
        }
    }

    #pragma unroll
    for (int i = 0; i < 8; i++) {
        const float bb = bias[c0 + i];
        #pragma unroll
        for (int j = 0; j < 8; j++)
            out[(n * C + c0 + i) * HW + p0 + pp0 + j] = acc[i][j] + bb;
    }
}

// ---------------------------------------------------------------------------
extern "C" void kernel_launch(void* const* d_in, const int* in_sizes, int n_in,
                              void* d_out, int out_size)
{
    const float* feat = (const float*)d_in[0];
    const float* wgt  = (const float*)d_in[1];
    const float* w1   = (const float*)d_in[2];
    const float* b1   = (const float*)d_in[3];
    const float* w2   = (const float*)d_in[4];
    const float* b2   = (const float*)d_in[5];
    const float* bbuf = (const float*)d_in[6];
    const float* coef = (const float*)d_in[7];
    const float* bias = (const float*)d_in[8];
    float* out = (float*)d_out;

    dim3 g1(1, H, N);
    k_conv1<<<g1, 256>>>(feat, wgt, w1, b1);

    k_conv2_bases<<<(N * HW) / 256, 256>>>(w2, b2, bbuf);

    k_bases_out<<<(N * HW) / 256, 256>>>(feat);

    dim3 g4(HW / 128, 1, N);
    k_out_gemm<<<g4, 256>>>(coef, bias, out);
}

// round 2
// speedup vs baseline: 1.0339x; 1.0339x over previous
#include <cuda_runtime.h>
#include <math.h>

// Problem constants
constexpr int N   = 8;
constexpr int C   = 128;
constexpr int CW  = 64;
constexpr int CIN = C + CW;   // 192
constexpr int H   = 96;
constexpr int W   = 96;
constexpr int HW  = H * W;    // 9216
constexpr int K768 = C * 6;   // 768

// Static scratch
__device__ float g_hmid [N * C * HW];             // 37.7 MB
__device__ float g_bases[N * 54 * HW];            // 15.9 MB
__device__ float g_v    [(size_t)N * K768 * HW];  // 226.5 MB  V[(c*6+m), p]

// ---------------------------------------------------------------------------
// Kernel 1: conv1 (3x3, 192->128) + tanh  -> g_hmid  (unchanged from R1)
// ---------------------------------------------------------------------------
__global__ __launch_bounds__(256) void k_conv1(
    const float* __restrict__ feat, const float* __restrict__ wgt,
    const float* __restrict__ w1,   const float* __restrict__ b1)
{
    const int n = blockIdx.z;
    const int y = blockIdx.y;
    const int tid = threadIdx.x;
    const int tx  = tid & 15;
    const int tco = tid >> 4;
    const int x0  = tx * 6;
    const int co0 = tco * 8;

    __shared__ float sIn[4 * 3 * 100];
    __shared__ float sW [4 * 9 * 132];

    float acc[8][6];
    #pragma unroll
    for (int i = 0; i < 8; i++)
        #pragma unroll
        for (int j = 0; j < 6; j++) acc[i][j] = 0.f;

    for (int cc = 0; cc < CIN; cc += 4) {
        __syncthreads();
        for (int i = tid; i < 4 * 3 * 98; i += 256) {
            int cil = i / 294;
            int rem = i - cil * 294;
            int r   = rem / 98;
            int xx  = rem - r * 98;
            int gy  = y + r - 1;
            int gx  = xx - 1;
            float v = 0.f;
            if (gy >= 0 && gy < H && gx >= 0 && gx < W) {
                int ci = cc + cil;
                v = (ci < C) ? feat[((n * C + ci) * H + gy) * W + gx]
                             : wgt [((n * CW + (ci - C)) * H + gy) * W + gx];
            }
            sIn[(cil * 3 + r) * 100 + xx] = v;
        }
        for (int i = tid; i < 128 * 36; i += 256) {
            int co  = i / 36;
            int rem = i - co * 36;
            int cil = rem / 9;
            int k   = rem - cil * 9;
            sW[(cil * 9 + k) * 132 + co] = w1[(co * CIN + cc + cil) * 9 + k];
        }
        __syncthreads();

        #pragma unroll
        for (int cil = 0; cil < 4; cil++) {
            #pragma unroll
            for (int ky = 0; ky < 3; ky++) {
                const float* rowp = &sIn[(cil * 3 + ky) * 100];
                #pragma unroll
                for (int kx = 0; kx < 3; kx++) {
                    const int k = ky * 3 + kx;
                    float a[8], b[6];
                    #pragma unroll
                    for (int i = 0; i < 8; i++) a[i] = sW[(cil * 9 + k) * 132 + co0 + i];
                    #pragma unroll
                    for (int j = 0; j < 6; j++) b[j] = rowp[x0 + kx + j];
                    #pragma unroll
                    for (int i = 0; i < 8; i++)
                        #pragma unroll
                        for (int j = 0; j < 6; j++)
                            acc[i][j] = fmaf(a[i], b[j], acc[i][j]);
                }
            }
        }
    }

    #pragma unroll
    for (int i = 0; i < 8; i++) {
        const float bb = b1[co0 + i];
        #pragma unroll
        for (int j = 0; j < 6; j++)
            g_hmid[((n * C + co0 + i) * H + y) * W + x0 + j] = tanhf(acc[i][j] + bb);
    }
}

// ---------------------------------------------------------------------------
// Kernel 2: conv2 (1x1, 128->36) + tanh, combine with FB bases -> g_bases
// ---------------------------------------------------------------------------
__global__ __launch_bounds__(256) void k_conv2_bases(
    const float* __restrict__ w2, const float* __restrict__ b2,
    const float* __restrict__ bbuf)
{
    __shared__ float sW2t[128 * 36];
    __shared__ float sBB[54];
    const int tid = threadIdx.x;

    for (int i = tid; i < 128 * 36; i += 256) {
        int ci = i / 36;
        int ch = i - ci * 36;
        sW2t[i] = w2[ch * 128 + ci];
    }
    if (tid < 54) sBB[tid] = bbuf[tid];
    __syncthreads();

    const int p  = blockIdx.x * 256 + tid;
    const int n  = p / HW;
    const int hw = p - n * HW;

    float acc[36];
    #pragma unroll
    for (int i = 0; i < 36; i++) acc[i] = 0.f;

    const float* hm = &g_hmid[(size_t)n * C * HW + hw];
    for (int ci = 0; ci < 128; ci++) {
        const float hv = hm[ci * HW];
        const float4* wrow = reinterpret_cast<const float4*>(&sW2t[ci * 36]);
        #pragma unroll
        for (int q = 0; q < 9; q++) {
            float4 w4 = wrow[q];
            acc[q * 4 + 0] = fmaf(w4.x, hv, acc[q * 4 + 0]);
            acc[q * 4 + 1] = fmaf(w4.y, hv, acc[q * 4 + 1]);
            acc[q * 4 + 2] = fmaf(w4.z, hv, acc[q * 4 + 2]);
            acc[q * 4 + 3] = fmaf(w4.w, hv, acc[q * 4 + 3]);
        }
    }

    float bv[36];
    #pragma unroll
    for (int i = 0; i < 36; i++) bv[i] = tanhf(acc[i] + b2[i]);

    #pragma unroll
    for (int m = 0; m < 6; m++) {
        #pragma unroll
        for (int l = 0; l < 9; l++) {
            float s = 0.f;
            #pragma unroll
            for (int t = 0; t < 6; t++) s = fmaf(bv[m * 6 + t], sBB[t * 9 + l], s);
            g_bases[(n * 54 + m * 9 + l) * HW + hw] = s;
        }
    }
}

// ---------------------------------------------------------------------------
// Kernel 3: V-GEMM.  V[(c*6+m), p] = sum_{c'} coef[c, c'*6+m] * feat[c', p]
// M=768, K=128, N=9216 per image.  128x128 tile, kt=16, double buffered.
// ---------------------------------------------------------------------------
__global__ __launch_bounds__(256) void k_vgemm(
    const float* __restrict__ coef, const float* __restrict__ feat)
{
    const int n  = blockIdx.z;
    const int r0 = blockIdx.y * 128;      // row (c*6+m) tile
    const int p0 = blockIdx.x * 128;      // pixel tile
    const int tid = threadIdx.x;
    const int tp = tid & 15;
    const int tc = tid >> 4;
    const int rr0 = tc * 8;
    const int pp0 = tp * 8;

    __shared__ float sA[2][16 * 132];   // [kk][row]
    __shared__ float sB[2][16 * 132];   // [kk][p]

    const float* Bp = feat + (size_t)n * C * HW + p0;

    float acc[8][8];
    #pragma unroll
    for (int i = 0; i < 8; i++)
        #pragma unroll
        for (int j = 0; j < 8; j++) acc[i][j] = 0.f;

    // chunk loader
    auto load_chunk = [&](int k0, int buf) {
        // A: 16 kk x 128 rows, gather from coef
        #pragma unroll
        for (int it = 0; it < 8; it++) {
            int i  = tid + it * 256;       // [0,2048)
            int kk = i >> 7;
            int row = i & 127;
            int rg = r0 + row;
            int c  = rg / 6;
            int m  = rg - c * 6;
            sA[buf][kk * 132 + row] = coef[c * K768 + (k0 + kk) * 6 + m];
        }
        // B: 16 kk x 128 px, float4
        #pragma unroll
        for (int it = 0; it < 2; it++) {
            int i  = tid + it * 256;       // [0,512) float4s
            int kk = i >> 5;
            int v  = i & 31;
            float4 t = *reinterpret_cast<const float4*>(&Bp[(size_t)(k0 + kk) * HW + v * 4]);
            *reinterpret_cast<float4*>(&sB[buf][kk * 132 + v * 4]) = t;
        }
    };

    load_chunk(0, 0);
    __syncthreads();

    int buf = 0;
    #pragma unroll
    for (int iter = 0; iter < 8; iter++) {
        if (iter + 1 < 8) load_chunk((iter + 1) * 16, buf ^ 1);
        #pragma unroll
        for (int kk = 0; kk < 16; kk++) {
            float a[8], b[8];
            #pragma unroll
            for (int i = 0; i < 8; i++) a[i] = sA[buf][kk * 132 + rr0 + i];
            #pragma unroll
            for (int j = 0; j < 8; j++) b[j] = sB[buf][kk * 132 + pp0 + j];
            #pragma unroll
            for (int i = 0; i < 8; i++)
                #pragma unroll
                for (int j = 0; j < 8; j++)
                    acc[i][j] = fmaf(a[i], b[j], acc[i][j]);
        }
        __syncthreads();
        buf ^= 1;
    }

    float* Vp = g_v + (size_t)n * K768 * HW + p0;
    #pragma unroll
    for (int i = 0; i < 8; i++)
        #pragma unroll
        for (int j = 0; j < 8; j += 4)
            *reinterpret_cast<float4*>(&Vp[(size_t)(r0 + rr0 + i) * HW + pp0 + j]) =
                make_float4(acc[i][j], acc[i][j+1], acc[i][j+2], acc[i][j+3]);
}

// ---------------------------------------------------------------------------
// Kernel 4: combine.  out[c,p] = bias[c] + sum_{m,l} bases[m,l,p] * V[(c6+m), p+off_l]
// One thread per pixel.
// ---------------------------------------------------------------------------
__global__ __launch_bounds__(256) void k_combine(
    const float* __restrict__ bias, float* __restrict__ out)
{
    const int p  = blockIdx.x * 256 + threadIdx.x;
    const int n  = p / HW;
    const int hw = p - n * HW;
    const int y  = hw / W;
    const int x  = hw - y * W;

    // per-pixel filter taps
    float bs[6][9];
    #pragma unroll
    for (int m = 0; m < 6; m++)
        #pragma unroll
        for (int l = 0; l < 9; l++)
            bs[m][l] = g_bases[(n * 54 + m * 9 + l) * HW + hw];

    // precompute shifted offsets + validity
    int  off[9];
    bool ok [9];
    #pragma unroll
    for (int l = 0; l < 9; l++) {
        const int dy = l / 3 - 1, dx = l % 3 - 1;
        off[l] = dy * W + dx;
        ok [l] = (unsigned)(y + dy) < (unsigned)H && (unsigned)(x + dx) < (unsigned)W;
    }

    const float* Vn = g_v + (size_t)n * K768 * HW + hw;
    float* on = out + (size_t)n * C * HW + hw;

    for (int c = 0; c < 128; c++) {
        float am[6];
        #pragma unroll
        for (int m = 0; m < 6; m++) {
            const float* row = Vn + (size_t)(c * 6 + m) * HW;
            float s = 0.f;
            #pragma unroll
            for (int l = 0; l < 9; l++) {
                float v = ok[l] ? __ldg(row + off[l]) : 0.f;
                s = fmaf(bs[m][l], v, s);
            }
            am[m] = s;
        }
        float r = ((am[0] + am[1]) + (am[2] + am[3])) + (am[4] + am[5]);
        on[(size_t)c * HW] = r + bias[c];
    }
}

// ---------------------------------------------------------------------------
extern "C" void kernel_launch(void* const* d_in, const int* in_sizes, int n_in,
                              void* d_out, int out_size)
{
    const float* feat = (const float*)d_in[0];
    const float* wgt  = (const float*)d_in[1];
    const float* w1   = (const float*)d_in[2];
    const float* b1   = (const float*)d_in[3];
    const float* w2   = (const float*)d_in[4];
    const float* b2   = (const float*)d_in[5];
    const float* bbuf = (const float*)d_in[6];
    const float* coef = (const float*)d_in[7];
    const float* bias = (const float*)d_in[8];
    float* out = (float*)d_out;

    dim3 g1(1, H, N);
    k_conv1<<<g1, 256>>>(feat, wgt, w1, b1);

    k_conv2_bases<<<(N * HW) / 256, 256>>>(w2, b2, bbuf);

    dim3 g3(HW / 128, K768 / 128, N);
    k_vgemm<<<g3, 256>>>(coef, feat);

    k_combine<<<(N * HW) / 256, 256>>>(bias, out);
}

// round 3
// speedup vs baseline: 1.2164x; 1.1766x over previous
#include <cuda_runtime.h>
#include <math.h>

// Problem constants
constexpr int N   = 8;
constexpr int C   = 128;
constexpr int CW  = 64;
constexpr int CIN = C + CW;   // 192
constexpr int H   = 96;
constexpr int W   = 96;
constexpr int HW  = H * W;    // 9216
constexpr int K768 = C * 6;   // 768

// Static scratch
__device__ float g_hmid [N * C * HW];             // 37.7 MB
__device__ float g_bases[N * 54 * HW];            // 15.9 MB
__device__ float g_v    [(size_t)N * K768 * HW];  // 226.5 MB  V[(c*6+m), p]

// ---------------------------------------------------------------------------
// Kernel 1: conv1 (3x3, 192->128) + tanh  -> g_hmid
// ---------------------------------------------------------------------------
__global__ __launch_bounds__(256) void k_conv1(
    const float* __restrict__ feat, const float* __restrict__ wgt,
    const float* __restrict__ w1,   const float* __restrict__ b1)
{
    const int n = blockIdx.z;
    const int y = blockIdx.y;
    const int tid = threadIdx.x;
    const int tx  = tid & 15;
    const int tco = tid >> 4;
    const int x0  = tx * 6;
    const int co0 = tco * 8;

    __shared__ float sIn[4 * 3 * 100];
    __shared__ float sW [4 * 9 * 132];

    float acc[8][6];
    #pragma unroll
    for (int i = 0; i < 8; i++)
        #pragma unroll
        for (int j = 0; j < 6; j++) acc[i][j] = 0.f;

    for (int cc = 0; cc < CIN; cc += 4) {
        __syncthreads();
        for (int i = tid; i < 4 * 3 * 98; i += 256) {
            int cil = i / 294;
            int rem = i - cil * 294;
            int r   = rem / 98;
            int xx  = rem - r * 98;
            int gy  = y + r - 1;
            int gx  = xx - 1;
            float v = 0.f;
            if (gy >= 0 && gy < H && gx >= 0 && gx < W) {
                int ci = cc + cil;
                v = (ci < C) ? feat[((n * C + ci) * H + gy) * W + gx]
                             : wgt [((n * CW + (ci - C)) * H + gy) * W + gx];
            }
            sIn[(cil * 3 + r) * 100 + xx] = v;
        }
        for (int i = tid; i < 128 * 36; i += 256) {
            int co  = i / 36;
            int rem = i - co * 36;
            int cil = rem / 9;
            int k   = rem - cil * 9;
            sW[(cil * 9 + k) * 132 + co] = w1[(co * CIN + cc + cil) * 9 + k];
        }
        __syncthreads();

        #pragma unroll
        for (int cil = 0; cil < 4; cil++) {
            #pragma unroll
            for (int ky = 0; ky < 3; ky++) {
                const float* rowp = &sIn[(cil * 3 + ky) * 100];
                #pragma unroll
                for (int kx = 0; kx < 3; kx++) {
                    const int k = ky * 3 + kx;
                    float a[8], b[6];
                    #pragma unroll
                    for (int i = 0; i < 8; i++) a[i] = sW[(cil * 9 + k) * 132 + co0 + i];
                    #pragma unroll
                    for (int j = 0; j < 6; j++) b[j] = rowp[x0 + kx + j];
                    #pragma unroll
                    for (int i = 0; i < 8; i++)
                        #pragma unroll
                        for (int j = 0; j < 6; j++)
                            acc[i][j] = fmaf(a[i], b[j], acc[i][j]);
                }
            }
        }
    }

    #pragma unroll
    for (int i = 0; i < 8; i++) {
        const float bb = b1[co0 + i];
        #pragma unroll
        for (int j = 0; j < 6; j++)
            g_hmid[((n * C + co0 + i) * H + y) * W + x0 + j] = tanhf(acc[i][j] + bb);
    }
}

// ---------------------------------------------------------------------------
// Kernel 2: conv2 (1x1, 128->36) + tanh, combine with FB bases -> g_bases
// ---------------------------------------------------------------------------
__global__ __launch_bounds__(256) void k_conv2_bases(
    const float* __restrict__ w2, const float* __restrict__ b2,
    const float* __restrict__ bbuf)
{
    __shared__ float sW2t[128 * 36];
    __shared__ float sBB[54];
    const int tid = threadIdx.x;

    for (int i = tid; i < 128 * 36; i += 256) {
        int ci = i / 36;
        int ch = i - ci * 36;
        sW2t[i] = w2[ch * 128 + ci];
    }
    if (tid < 54) sBB[tid] = bbuf[tid];
    __syncthreads();

    const int p  = blockIdx.x * 256 + tid;
    const int n  = p / HW;
    const int hw = p - n * HW;

    float acc[36];
    #pragma unroll
    for (int i = 0; i < 36; i++) acc[i] = 0.f;

    const float* hm = &g_hmid[(size_t)n * C * HW + hw];
    for (int ci = 0; ci < 128; ci++) {
        const float hv = hm[ci * HW];
        const float4* wrow = reinterpret_cast<const float4*>(&sW2t[ci * 36]);
        #pragma unroll
        for (int q = 0; q < 9; q++) {
            float4 w4 = wrow[q];
            acc[q * 4 + 0] = fmaf(w4.x, hv, acc[q * 4 + 0]);
            acc[q * 4 + 1] = fmaf(w4.y, hv, acc[q * 4 + 1]);
            acc[q * 4 + 2] = fmaf(w4.z, hv, acc[q * 4 + 2]);
            acc[q * 4 + 3] = fmaf(w4.w, hv, acc[q * 4 + 3]);
        }
    }

    float bv[36];
    #pragma unroll
    for (int i = 0; i < 36; i++) bv[i] = tanhf(acc[i] + b2[i]);

    #pragma unroll
    for (int m = 0; m < 6; m++) {
        #pragma unroll
        for (int l = 0; l < 9; l++) {
            float s = 0.f;
            #pragma unroll
            for (int t = 0; t < 6; t++) s = fmaf(bv[m * 6 + t], sBB[t * 9 + l], s);
            g_bases[(n * 54 + m * 9 + l) * HW + hw] = s;
        }
    }
}

// ---------------------------------------------------------------------------
// Kernel 3: V-GEMM.  V[(c*6+m), p] = sum_{c'} coef[c, c'*6+m] * feat[c', p]
// ---------------------------------------------------------------------------
__global__ __launch_bounds__(256) void k_vgemm(
    const float* __restrict__ coef, const float* __restrict__ feat)
{
    const int n  = blockIdx.z;
    const int r0 = blockIdx.y * 128;
    const int p0 = blockIdx.x * 128;
    const int tid = threadIdx.x;
    const int tp = tid & 15;
    const int tc = tid >> 4;
    const int rr0 = tc * 8;
    const int pp0 = tp * 8;

    __shared__ float sA[2][16 * 132];
    __shared__ float sB[2][16 * 132];

    const float* Bp = feat + (size_t)n * C * HW + p0;

    float acc[8][8];
    #pragma unroll
    for (int i = 0; i < 8; i++)
        #pragma unroll
        for (int j = 0; j < 8; j++) acc[i][j] = 0.f;

    auto load_chunk = [&](int k0, int buf) {
        #pragma unroll
        for (int it = 0; it < 8; it++) {
            int i  = tid + it * 256;
            int kk = i >> 7;
            int row = i & 127;
            int rg = r0 + row;
            int c  = rg / 6;
            int m  = rg - c * 6;
            sA[buf][kk * 132 + row] = coef[c * K768 + (k0 + kk) * 6 + m];
        }
        #pragma unroll
        for (int it = 0; it < 2; it++) {
            int i  = tid + it * 256;
            int kk = i >> 5;
            int v  = i & 31;
            float4 t = *reinterpret_cast<const float4*>(&Bp[(size_t)(k0 + kk) * HW + v * 4]);
            *reinterpret_cast<float4*>(&sB[buf][kk * 132 + v * 4]) = t;
        }
    };

    load_chunk(0, 0);
    __syncthreads();

    int buf = 0;
    #pragma unroll
    for (int iter = 0; iter < 8; iter++) {
        if (iter + 1 < 8) load_chunk((iter + 1) * 16, buf ^ 1);
        #pragma unroll
        for (int kk = 0; kk < 16; kk++) {
            float a[8], b[8];
            #pragma unroll
            for (int i = 0; i < 8; i++) a[i] = sA[buf][kk * 132 + rr0 + i];
            #pragma unroll
            for (int j = 0; j < 8; j++) b[j] = sB[buf][kk * 132 + pp0 + j];
            #pragma unroll
            for (int i = 0; i < 8; i++)
                #pragma unroll
                for (int j = 0; j < 8; j++)
                    acc[i][j] = fmaf(a[i], b[j], acc[i][j]);
        }
        __syncthreads();
        buf ^= 1;
    }

    float* Vp = g_v + (size_t)n * K768 * HW + p0;
    #pragma unroll
    for (int i = 0; i < 8; i++)
        #pragma unroll
        for (int j = 0; j < 8; j += 4)
            *reinterpret_cast<float4*>(&Vp[(size_t)(r0 + rr0 + i) * HW + pp0 + j]) =
                make_float4(acc[i][j], acc[i][j+1], acc[i][j+2], acc[i][j+3]);
}

// ---------------------------------------------------------------------------
// Kernel 4: combine, c-split for occupancy.
// grid (N*HW/256, 8); block handles 16 channels for 256 pixels.
// out[c,p] = bias[c] + sum_{m,l} bases[m,l,p] * V[(c6+m), p+off_l]
// ---------------------------------------------------------------------------
__global__ __launch_bounds__(256) void k_combine(
    const float* __restrict__ bias, float* __restrict__ out)
{
    const int p  = blockIdx.x * 256 + threadIdx.x;
    const int cb = blockIdx.y * 16;           // channel chunk start
    const int n  = p / HW;
    const int hw = p - n * HW;
    const int y  = hw / W;
    const int x  = hw - y * W;

    // per-pixel filter taps
    float bs[6][9];
    #pragma unroll
    for (int m = 0; m < 6; m++)
        #pragma unroll
        for (int l = 0; l < 9; l++)
            bs[m][l] = __ldg(&g_bases[(n * 54 + m * 9 + l) * HW + hw]);

    int  off[9];
    #pragma unroll
    for (int l = 0; l < 9; l++) {
        const int dy = l / 3 - 1, dx = l % 3 - 1;
        off[l] = dy * W + dx;
        const bool ok = (unsigned)(y + dy) < (unsigned)H && (unsigned)(x + dx) < (unsigned)W;
        // fold validity into the taps so inner loop is pure FMA+LDG
        if (!ok) {
            #pragma unroll
            for (int m = 0; m < 6; m++) bs[m][l] = 0.f;
            off[l] = 0;  // safe in-bounds read, multiplied by 0
        }
    }

    const float* Vn = g_v + (size_t)n * K768 * HW + hw;
    float* on = out + (size_t)n * C * HW + hw;

    #pragma unroll 4
    for (int ci = 0; ci < 16; ci++) {
        const int c = cb + ci;
        float am[6];
        #pragma unroll
        for (int m = 0; m < 6; m++) {
            const float* row = Vn + (size_t)(c * 6 + m) * HW;
            float s = 0.f;
            #pragma unroll
            for (int l = 0; l < 9; l++)
                s = fmaf(bs[m][l], __ldg(row + off[l]), s);
            am[m] = s;
        }
        float r = ((am[0] + am[1]) + (am[2] + am[3])) + (am[4] + am[5]);
        on[(size_t)c * HW] = r + __ldg(&bias[c]);
    }
}

// ---------------------------------------------------------------------------
extern "C" void kernel_launch(void* const* d_in, const int* in_sizes, int n_in,
                              void* d_out, int out_size)
{
    const float* feat = (const float*)d_in[0];
    const float* wgt  = (const float*)d_in[1];
    const float* w1   = (const float*)d_in[2];
    const float* b1   = (const float*)d_in[3];
    const float* w2   = (const float*)d_in[4];
    const float* b2   = (const float*)d_in[5];
    const float* bbuf = (const float*)d_in[6];
    const float* coef = (const float*)d_in[7];
    const float* bias = (const float*)d_in[8];
    float* out = (float*)d_out;

    dim3 g1(1, H, N);
    k_conv1<<<g1, 256>>>(feat, wgt, w1, b1);

    k_conv2_bases<<<(N * HW) / 256, 256>>>(w2, b2, bbuf);

    dim3 g3(HW / 128, K768 / 128, N);
    k_vgemm<<<g3, 256>>>(coef, feat);

    dim3 g4((N * HW) / 256, 8);
    k_combine<<<g4, 256>>>(bias, out);
}

// round 4
// speedup vs baseline: 1.2877x; 1.0586x over previous
#include <cuda_runtime.h>
#include <math.h>

// Problem constants
constexpr int N   = 8;
constexpr int C   = 128;
constexpr int CW  = 64;
constexpr int CIN = C + CW;   // 192
constexpr int H   = 96;
constexpr int W   = 96;
constexpr int HW  = H * W;    // 9216
constexpr int K768 = C * 6;   // 768

// Static scratch
__device__ float g_bases[N * 54 * HW];            // 15.9 MB
__device__ float g_v    [(size_t)N * K768 * HW];  // 226.5 MB  V[(c*6+m), p]

// Dynamic smem layout (floats)
constexpr int SM_IN  = 0;       // 4*3*100 = 1200   (mainloop input tile)
constexpr int SM_W   = 1200;    // 36*132  = 4752   (mainloop weights)
constexpr int SM_BV  = 0;       // 96*37   = 3552   (conv2 outputs; reuses IN/W region)
constexpr int SM_H   = 5952;    // 128*97  = 12416  (hmid tile)
constexpr int SM_W2  = 18368;   // 128*36  = 4608   (W2 transposed [ci][ch])
constexpr int SM_BB  = 22976;   // 54
constexpr int SM_TOT = 23032;   // floats
constexpr int SM_BYTES = SM_TOT * 4;  // 92128 B

// ---------------------------------------------------------------------------
// Kernel 1: conv1(3x3,192->128)+tanh  FUSED with conv2(1x1,128->36)+tanh and
// FB-basis combine. One block per (n, y); writes g_bases directly.
// ---------------------------------------------------------------------------
__global__ __launch_bounds__(256) void k_conv1_fused(
    const float* __restrict__ feat, const float* __restrict__ wgt,
    const float* __restrict__ w1,   const float* __restrict__ b1,
    const float* __restrict__ w2,   const float* __restrict__ b2,
    const float* __restrict__ bbuf)
{
    extern __shared__ float smem[];
    float* sIn = smem + SM_IN;
    float* sW  = smem + SM_W;
    float* sBv = smem + SM_BV;
    float* sH  = smem + SM_H;
    float* sW2 = smem + SM_W2;
    float* sBB = smem + SM_BB;

    const int n = blockIdx.z;
    const int y = blockIdx.y;
    const int tid = threadIdx.x;
    const int tx  = tid & 15;
    const int tco = tid >> 4;
    const int x0  = tx * 6;
    const int co0 = tco * 8;

    // Preload W2 (transposed to [ci][ch]) and FB bases (regions disjoint from mainloop)
    for (int i = tid; i < 128 * 36; i += 256) {
        int ci = i / 36;
        int ch = i - ci * 36;
        sW2[i] = w2[ch * 128 + ci];
    }
    if (tid < 54) sBB[tid] = bbuf[tid];

    float acc[8][6];
    #pragma unroll
    for (int i = 0; i < 8; i++)
        #pragma unroll
        for (int j = 0; j < 6; j++) acc[i][j] = 0.f;

    for (int cc = 0; cc < CIN; cc += 4) {
        __syncthreads();
        for (int i = tid; i < 4 * 3 * 98; i += 256) {
            int cil = i / 294;
            int rem = i - cil * 294;
            int r   = rem / 98;
            int xx  = rem - r * 98;
            int gy  = y + r - 1;
            int gx  = xx - 1;
            float v = 0.f;
            if (gy >= 0 && gy < H && gx >= 0 && gx < W) {
                int ci = cc + cil;
                v = (ci < C) ? feat[((n * C + ci) * H + gy) * W + gx]
                             : wgt [((n * CW + (ci - C)) * H + gy) * W + gx];
            }
            sIn[(cil * 3 + r) * 100 + xx] = v;
        }
        for (int i = tid; i < 128 * 36; i += 256) {
            int co  = i / 36;
            int rem = i - co * 36;
            int cil = rem / 9;
            int k   = rem - cil * 9;
            sW[(cil * 9 + k) * 132 + co] = w1[(co * CIN + cc + cil) * 9 + k];
        }
        __syncthreads();

        #pragma unroll
        for (int cil = 0; cil < 4; cil++) {
            #pragma unroll
            for (int ky = 0; ky < 3; ky++) {
                const float* rowp = &sIn[(cil * 3 + ky) * 100];
                #pragma unroll
                for (int kx = 0; kx < 3; kx++) {
                    const int k = ky * 3 + kx;
                    float a[8], b[6];
                    #pragma unroll
                    for (int i = 0; i < 8; i++) a[i] = sW[(cil * 9 + k) * 132 + co0 + i];
                    #pragma unroll
                    for (int j = 0; j < 6; j++) b[j] = rowp[x0 + kx + j];
                    #pragma unroll
                    for (int i = 0; i < 8; i++)
                        #pragma unroll
                        for (int j = 0; j < 6; j++)
                            acc[i][j] = fmaf(a[i], b[j], acc[i][j]);
                }
            }
        }
    }

    // hmid -> shared (tanh applied); no gmem round-trip
    #pragma unroll
    for (int i = 0; i < 8; i++) {
        const float bb1 = b1[co0 + i];
        #pragma unroll
        for (int j = 0; j < 6; j++)
            sH[(co0 + i) * 97 + x0 + j] = tanhf(acc[i][j] + bb1);
    }
    __syncthreads();

    // conv2: 2 threads per pixel, 18 channels each (192 active threads)
    if (tid < 192) {
        const int px  = tid >> 1;
        const int ch0 = (tid & 1) * 18;
        float a2[18];
        #pragma unroll
        for (int k = 0; k < 18; k++) a2[k] = 0.f;
        for (int ci = 0; ci < 128; ci++) {
            const float hv = sH[ci * 97 + px];
            const float2* wr = reinterpret_cast<const float2*>(&sW2[ci * 36 + ch0]);
            #pragma unroll
            for (int q = 0; q < 9; q++) {
                float2 wv = wr[q];
                a2[2 * q + 0] = fmaf(wv.x, hv, a2[2 * q + 0]);
                a2[2 * q + 1] = fmaf(wv.y, hv, a2[2 * q + 1]);
            }
        }
        #pragma unroll
        for (int k = 0; k < 18; k++)
            sBv[px * 37 + ch0 + k] = tanhf(a2[k] + b2[ch0 + k]);
    }
    __syncthreads();

    // FB-basis combine -> g_bases[(n*54 + m*9+l)][y*W + px]
    for (int i = tid; i < 54 * 96; i += 256) {
        const int j  = i / 96;          // m*9 + l
        const int px = i - j * 96;
        const int m  = j / 9;
        const int l  = j - m * 9;
        float s = 0.f;
        #pragma unroll
        for (int t = 0; t < 6; t++)
            s = fmaf(sBv[px * 37 + m * 6 + t], sBB[t * 9 + l], s);
        g_bases[(n * 54 + j) * HW + y * W + px] = s;
    }
}

// ---------------------------------------------------------------------------
// Kernel 2: V-GEMM.  V[(c*6+m), p] = sum_{c'} coef[c, c'*6+m] * feat[c', p]
// ---------------------------------------------------------------------------
__global__ __launch_bounds__(256) void k_vgemm(
    const float* __restrict__ coef, const float* __restrict__ feat)
{
    const int n  = blockIdx.z;
    const int r0 = blockIdx.y * 128;
    const int p0 = blockIdx.x * 128;
    const int tid = threadIdx.x;
    const int tp = tid & 15;
    const int tc = tid >> 4;
    const int rr0 = tc * 8;
    const int pp0 = tp * 8;

    __shared__ float sA[2][16 * 132];
    __shared__ float sB[2][16 * 132];

    const float* Bp = feat + (size_t)n * C * HW + p0;

    float acc[8][8];
    #pragma unroll
    for (int i = 0; i < 8; i++)
        #pragma unroll
        for (int j = 0; j < 8; j++) acc[i][j] = 0.f;

    auto load_chunk = [&](int k0, int buf) {
        #pragma unroll
        for (int it = 0; it < 8; it++) {
            int i  = tid + it * 256;
            int kk = i >> 7;
            int row = i & 127;
            int rg = r0 + row;
            int c  = rg / 6;
            int m  = rg - c * 6;
            sA[buf][kk * 132 + row] = coef[c * K768 + (k0 + kk) * 6 + m];
        }
        #pragma unroll
        for (int it = 0; it < 2; it++) {
            int i  = tid + it * 256;
            int kk = i >> 5;
            int v  = i & 31;
            float4 t = *reinterpret_cast<const float4*>(&Bp[(size_t)(k0 + kk) * HW + v * 4]);
            *reinterpret_cast<float4*>(&sB[buf][kk * 132 + v * 4]) = t;
        }
    };

    load_chunk(0, 0);
    __syncthreads();

    int buf = 0;
    #pragma unroll
    for (int iter = 0; iter < 8; iter++) {
        if (iter + 1 < 8) load_chunk((iter + 1) * 16, buf ^ 1);
        #pragma unroll
        for (int kk = 0; kk < 16; kk++) {
            float a[8], b[8];
            #pragma unroll
            for (int i = 0; i < 8; i++) a[i] = sA[buf][kk * 132 + rr0 + i];
            #pragma unroll
            for (int j = 0; j < 8; j++) b[j] = sB[buf][kk * 132 + pp0 + j];
            #pragma unroll
            for (int i = 0; i < 8; i++)
                #pragma unroll
                for (int j = 0; j < 8; j++)
                    acc[i][j] = fmaf(a[i], b[j], acc[i][j]);
        }
        __syncthreads();
        buf ^= 1;
    }

    float* Vp = g_v + (size_t)n * K768 * HW + p0;
    #pragma unroll
    for (int i = 0; i < 8; i++)
        #pragma unroll
        for (int j = 0; j < 8; j += 4)
            *reinterpret_cast<float4*>(&Vp[(size_t)(r0 + rr0 + i) * HW + pp0 + j]) =
                make_float4(acc[i][j], acc[i][j+1], acc[i][j+2], acc[i][j+3]);
}

// ---------------------------------------------------------------------------
// Kernel 3: combine (c-split).
// out[c,p] = bias[c] + sum_{m,l} bases[m,l,p] * V[(c6+m), p+off_l]
// ---------------------------------------------------------------------------
__global__ __launch_bounds__(256) void k_combine(
    const float* __restrict__ bias, float* __restrict__ out)
{
    const int p  = blockIdx.x * 256 + threadIdx.x;
    const int cb = blockIdx.y * 16;
    const int n  = p / HW;
    const int hw = p - n * HW;
    const int y  = hw / W;
    const int x  = hw - y * W;

    float bs[6][9];
    #pragma unroll
    for (int m = 0; m < 6; m++)
        #pragma unroll
        for (int l = 0; l < 9; l++)
            bs[m][l] = __ldg(&g_bases[(n * 54 + m * 9 + l) * HW + hw]);

    int  off[9];
    #pragma unroll
    for (int l = 0; l < 9; l++) {
        const int dy = l / 3 - 1, dx = l % 3 - 1;
        off[l] = dy * W + dx;
        const bool ok = (unsigned)(y + dy) < (unsigned)H && (unsigned)(x + dx) < (unsigned)W;
        if (!ok) {
            #pragma unroll
            for (int m = 0; m < 6; m++) bs[m][l] = 0.f;
            off[l] = 0;
        }
    }

    const float* Vn = g_v + (size_t)n * K768 * HW + hw;
    float* on = out + (size_t)n * C * HW + hw;

    #pragma unroll 4
    for (int ci = 0; ci < 16; ci++) {
        const int c = cb + ci;
        float am[6];
        #pragma unroll
        for (int m = 0; m < 6; m++) {
            const float* row = Vn + (size_t)(c * 6 + m) * HW;
            float s = 0.f;
            #pragma unroll
            for (int l = 0; l < 9; l++)
                s = fmaf(bs[m][l], __ldg(row + off[l]), s);
            am[m] = s;
        }
        float r = ((am[0] + am[1]) + (am[2] + am[3])) + (am[4] + am[5]);
        on[(size_t)c * HW] = r + __ldg(&bias[c]);
    }
}

// ---------------------------------------------------------------------------
extern "C" void kernel_launch(void* const* d_in, const int* in_sizes, int n_in,
                              void* d_out, int out_size)
{
    const float* feat = (const float*)d_in[0];
    const float* wgt  = (const float*)d_in[1];
    const float* w1   = (const float*)d_in[2];
    const float* b1   = (const float*)d_in[3];
    const float* w2   = (const float*)d_in[4];
    const float* b2   = (const float*)d_in[5];
    const float* bbuf = (const float*)d_in[6];
    const float* coef = (const float*)d_in[7];
    const float* bias = (const float*)d_in[8];
    float* out = (float*)d_out;

    static bool attr_set = false;
    if (!attr_set) {
        cudaFuncSetAttribute(k_conv1_fused,
                             cudaFuncAttributeMaxDynamicSharedMemorySize, SM_BYTES);
        attr_set = true;
    }

    dim3 g1(1, H, N);
    k_conv1_fused<<<g1, 256, SM_BYTES>>>(feat, wgt, w1, b1, w2, b2, bbuf);

    dim3 g3(HW / 128, K768 / 128, N);
    k_vgemm<<<g3, 256>>>(coef, feat);

    dim3 g4((N * HW) / 256, 8);
    k_combine<<<g4, 256>>>(bias, out);
}

// round 5
// speedup vs baseline: 1.3675x; 1.0620x over previous
#include <cuda_runtime.h>
#include <math.h>

typedef unsigned long long u64;

__device__ __forceinline__ u64 pack2(float lo, float hi) {
    u64 r; asm("mov.b64 %0, {%1, %2};" : "=l"(r) : "f"(lo), "f"(hi)); return r;
}
__device__ __forceinline__ void ffma2(u64& d, u64 a, u64 b) {
    asm("fma.rn.f32x2 %0, %1, %2, %3;" : "=l"(d) : "l"(a), "l"(b), "l"(d));
}
__device__ __forceinline__ float2 unpack2(u64 v) {
    float2 r; asm("mov.b64 {%0, %1}, %2;" : "=f"(r.x), "=f"(r.y) : "l"(v)); return r;
}

// Problem constants
constexpr int N   = 8;
constexpr int C   = 128;
constexpr int CW  = 64;
constexpr int CIN = C + CW;   // 192
constexpr int H   = 96;
constexpr int W   = 96;
constexpr int HW  = H * W;    // 9216
constexpr int K768 = C * 6;   // 768

// Static scratch
__device__ float g_bases[N * 54 * HW];            // 15.9 MB
__device__ float g_v    [(size_t)N * K768 * HW];  // 226.5 MB  V[(c*6+m), p]

// Dynamic smem layout (floats)
constexpr int SM_IN  = 0;       // 4*3*100 = 1200
constexpr int SM_W   = 1200;    // 36*132  = 4752
constexpr int SM_BV  = 0;       // 96*37   = 3552 (reuses IN/W region)
constexpr int SM_H   = 5952;    // 128*97  = 12416
constexpr int SM_W2  = 18368;   // 128*36  = 4608
constexpr int SM_BB  = 22976;   // 54
constexpr int SM_TOT = 23032;
constexpr int SM_BYTES = SM_TOT * 4;  // 92128 B

// ---------------------------------------------------------------------------
// Kernel 1: conv1(3x3,192->128)+tanh FUSED with conv2(1x1,128->36)+tanh and
// FB-basis combine. One block per (n, y). FFMA2 mainloop.
// ---------------------------------------------------------------------------
__global__ __launch_bounds__(256) void k_conv1_fused(
    const float* __restrict__ feat, const float* __restrict__ wgt,
    const float* __restrict__ w1,   const float* __restrict__ b1,
    const float* __restrict__ w2,   const float* __restrict__ b2,
    const float* __restrict__ bbuf)
{
    extern __shared__ float smem[];
    float* sIn = smem + SM_IN;
    float* sW  = smem + SM_W;
    float* sBv = smem + SM_BV;
    float* sH  = smem + SM_H;
    float* sW2 = smem + SM_W2;
    float* sBB = smem + SM_BB;

    const int n = blockIdx.z;
    const int y = blockIdx.y;
    const int tid = threadIdx.x;
    const int tx  = tid & 15;
    const int tco = tid >> 4;
    const int x0  = tx * 6;
    const int co0 = tco * 8;

    for (int i = tid; i < 128 * 36; i += 256) {
        int ci = i / 36;
        int ch = i - ci * 36;
        sW2[i] = w2[ch * 128 + ci];
    }
    if (tid < 54) sBB[tid] = bbuf[tid];

    u64 acc2[4][6];
    #pragma unroll
    for (int i = 0; i < 4; i++)
        #pragma unroll
        for (int j = 0; j < 6; j++) acc2[i][j] = 0ULL;

    for (int cc = 0; cc < CIN; cc += 4) {
        __syncthreads();
        for (int i = tid; i < 4 * 3 * 98; i += 256) {
            int cil = i / 294;
            int rem = i - cil * 294;
            int r   = rem / 98;
            int xx  = rem - r * 98;
            int gy  = y + r - 1;
            int gx  = xx - 1;
            float v = 0.f;
            if (gy >= 0 && gy < H && gx >= 0 && gx < W) {
                int ci = cc + cil;
                v = (ci < C) ? feat[((n * C + ci) * H + gy) * W + gx]
                             : wgt [((n * CW + (ci - C)) * H + gy) * W + gx];
            }
            sIn[(cil * 3 + r) * 100 + xx] = v;
        }
        for (int i = tid; i < 128 * 36; i += 256) {
            int co  = i / 36;
            int rem = i - co * 36;
            int cil = rem / 9;
            int k   = rem - cil * 9;
            sW[(cil * 9 + k) * 132 + co] = w1[(co * CIN + cc + cil) * 9 + k];
        }
        __syncthreads();

        #pragma unroll
        for (int cil = 0; cil < 4; cil++) {
            #pragma unroll
            for (int ky = 0; ky < 3; ky++) {
                const float* rowp = &sIn[(cil * 3 + ky) * 100];
                // broadcast-packed input values x0 .. x0+7
                u64 bp[8];
                #pragma unroll
                for (int v = 0; v < 8; v++) {
                    float t = rowp[x0 + v];
                    bp[v] = pack2(t, t);
                }
                #pragma unroll
                for (int kx = 0; kx < 3; kx++) {
                    const int k = ky * 3 + kx;
                    u64 a2[4];
                    #pragma unroll
                    for (int ip = 0; ip < 4; ip++)
                        a2[ip] = *reinterpret_cast<const u64*>(
                            &sW[(cil * 9 + k) * 132 + co0 + 2 * ip]);
                    #pragma unroll
                    for (int ip = 0; ip < 4; ip++)
                        #pragma unroll
                        for (int j = 0; j < 6; j++)
                            ffma2(acc2[ip][j], a2[ip], bp[kx + j]);
                }
            }
        }
    }

    // hmid -> shared (tanh applied)
    #pragma unroll
    for (int ip = 0; ip < 4; ip++) {
        const float bb0 = b1[co0 + 2 * ip];
        const float bb1 = b1[co0 + 2 * ip + 1];
        #pragma unroll
        for (int j = 0; j < 6; j++) {
            float2 v = unpack2(acc2[ip][j]);
            sH[(co0 + 2 * ip)     * 97 + x0 + j] = tanhf(v.x + bb0);
            sH[(co0 + 2 * ip + 1) * 97 + x0 + j] = tanhf(v.y + bb1);
        }
    }
    __syncthreads();

    // conv2: 2 threads per pixel, 18 channels each (as 9 packed pairs)
    if (tid < 192) {
        const int px  = tid >> 1;
        const int ch0 = (tid & 1) * 18;
        u64 a2c[9];
        #pragma unroll
        for (int q = 0; q < 9; q++) a2c[q] = 0ULL;
        for (int ci = 0; ci < 128; ci++) {
            const float hv = sH[ci * 97 + px];
            const u64 hb = pack2(hv, hv);
            const u64* wr = reinterpret_cast<const u64*>(&sW2[ci * 36 + ch0]);
            #pragma unroll
            for (int q = 0; q < 9; q++)
                ffma2(a2c[q], wr[q], hb);
        }
        #pragma unroll
        for (int q = 0; q < 9; q++) {
            float2 v = unpack2(a2c[q]);
            sBv[px * 37 + ch0 + 2 * q]     = tanhf(v.x + b2[ch0 + 2 * q]);
            sBv[px * 37 + ch0 + 2 * q + 1] = tanhf(v.y + b2[ch0 + 2 * q + 1]);
        }
    }
    __syncthreads();

    // FB-basis combine -> g_bases
    for (int i = tid; i < 54 * 96; i += 256) {
        const int j  = i / 96;
        const int px = i - j * 96;
        const int m  = j / 9;
        const int l  = j - m * 9;
        float s = 0.f;
        #pragma unroll
        for (int t = 0; t < 6; t++)
            s = fmaf(sBv[px * 37 + m * 6 + t], sBB[t * 9 + l], s);
        g_bases[(n * 54 + j) * HW + y * W + px] = s;
    }
}

// ---------------------------------------------------------------------------
// Kernel 2: V-GEMM with FFMA2.  V[(c*6+m), p] = sum_{c'} coef[c, c'*6+m] * feat[c', p]
// ---------------------------------------------------------------------------
__global__ __launch_bounds__(256) void k_vgemm(
    const float* __restrict__ coef, const float* __restrict__ feat)
{
    const int n  = blockIdx.z;
    const int r0 = blockIdx.y * 128;
    const int p0 = blockIdx.x * 128;
    const int tid = threadIdx.x;
    const int tp = tid & 15;
    const int tc = tid >> 4;
    const int rr0 = tc * 8;
    const int pp0 = tp * 8;

    __shared__ float sA[2][16 * 132];
    __shared__ float sB[2][16 * 132];

    const float* Bp = feat + (size_t)n * C * HW + p0;

    u64 acc2[8][4];
    #pragma unroll
    for (int i = 0; i < 8; i++)
        #pragma unroll
        for (int j = 0; j < 4; j++) acc2[i][j] = 0ULL;

    auto load_chunk = [&](int k0, int buf) {
        #pragma unroll
        for (int it = 0; it < 8; it++) {
            int i  = tid + it * 256;
            int kk = i >> 7;
            int row = i & 127;
            int rg = r0 + row;
            int c  = rg / 6;
            int m  = rg - c * 6;
            sA[buf][kk * 132 + row] = coef[c * K768 + (k0 + kk) * 6 + m];
        }
        #pragma unroll
        for (int it = 0; it < 2; it++) {
            int i  = tid + it * 256;
            int kk = i >> 5;
            int v  = i & 31;
            float4 t = *reinterpret_cast<const float4*>(&Bp[(size_t)(k0 + kk) * HW + v * 4]);
            *reinterpret_cast<float4*>(&sB[buf][kk * 132 + v * 4]) = t;
        }
    };

    load_chunk(0, 0);
    __syncthreads();

    int buf = 0;
    #pragma unroll
    for (int iter = 0; iter < 8; iter++) {
        if (iter + 1 < 8) load_chunk((iter + 1) * 16, buf ^ 1);
        #pragma unroll
        for (int kk = 0; kk < 16; kk++) {
            u64 ab[8], b2v[4];
            #pragma unroll
            for (int i = 0; i < 8; i++) {
                float a = sA[buf][kk * 132 + rr0 + i];
                ab[i] = pack2(a, a);
            }
            #pragma unroll
            for (int jp = 0; jp < 4; jp++)
                b2v[jp] = *reinterpret_cast<const u64*>(&sB[buf][kk * 132 + pp0 + 2 * jp]);
            #pragma unroll
            for (int i = 0; i < 8; i++)
                #pragma unroll
                for (int jp = 0; jp < 4; jp++)
                    ffma2(acc2[i][jp], ab[i], b2v[jp]);
        }
        __syncthreads();
        buf ^= 1;
    }

    float* Vp = g_v + (size_t)n * K768 * HW + p0;
    #pragma unroll
    for (int i = 0; i < 8; i++) {
        float2 v0 = unpack2(acc2[i][0]);
        float2 v1 = unpack2(acc2[i][1]);
        float2 v2 = unpack2(acc2[i][2]);
        float2 v3 = unpack2(acc2[i][3]);
        *reinterpret_cast<float4*>(&Vp[(size_t)(r0 + rr0 + i) * HW + pp0]) =
            make_float4(v0.x, v0.y, v1.x, v1.y);
        *reinterpret_cast<float4*>(&Vp[(size_t)(r0 + rr0 + i) * HW + pp0 + 4]) =
            make_float4(v2.x, v2.y, v3.x, v3.y);
    }
}

// ---------------------------------------------------------------------------
// Kernel 3: combine (c-split).
// ---------------------------------------------------------------------------
__global__ __launch_bounds__(256) void k_combine(
    const float* __restrict__ bias, float* __restrict__ out)
{
    const int p  = blockIdx.x * 256 + threadIdx.x;
    const int cb = blockIdx.y * 16;
    const int n  = p / HW;
    const int hw = p - n * HW;
    const int y  = hw / W;
    const int x  = hw - y * W;

    float bs[6][9];
    #pragma unroll
    for (int m = 0; m < 6; m++)
        #pragma unroll
        for (int l = 0; l < 9; l++)
            bs[m][l] = __ldg(&g_bases[(n * 54 + m * 9 + l) * HW + hw]);

    int  off[9];
    #pragma unroll
    for (int l = 0; l < 9; l++) {
        const int dy = l / 3 - 1, dx = l % 3 - 1;
        off[l] = dy * W + dx;
        const bool ok = (unsigned)(y + dy) < (unsigned)H && (unsigned)(x + dx) < (unsigned)W;
        if (!ok) {
            #pragma unroll
            for (int m = 0; m < 6; m++) bs[m][l] = 0.f;
            off[l] = 0;
        }
    }

    const float* Vn = g_v + (size_t)n * K768 * HW + hw;
    float* on = out + (size_t)n * C * HW + hw;

    #pragma unroll 4
    for (int ci = 0; ci < 16; ci++) {
        const int c = cb + ci;
        float am[6];
        #pragma unroll
        for (int m = 0; m < 6; m++) {
            const float* row = Vn + (size_t)(c * 6 + m) * HW;
            float s = 0.f;
            #pragma unroll
            for (int l = 0; l < 9; l++)
                s = fmaf(bs[m][l], __ldg(row + off[l]), s);
            am[m] = s;
        }
        float r = ((am[0] + am[1]) + (am[2] + am[3])) + (am[4] + am[5]);
        on[(size_t)c * HW] = r + __ldg(&bias[c]);
    }
}

// ---------------------------------------------------------------------------
extern "C" void kernel_launch(void* const* d_in, const int* in_sizes, int n_in,
                              void* d_out, int out_size)
{
    const float* feat = (const float*)d_in[0];
    const float* wgt  = (const float*)d_in[1];
    const float* w1   = (const float*)d_in[2];
    const float* b1   = (const float*)d_in[3];
    const float* w2   = (const float*)d_in[4];
    const float* b2   = (const float*)d_in[5];
    const float* bbuf = (const float*)d_in[6];
    const float* coef = (const float*)d_in[7];
    const float* bias = (const float*)d_in[8];
    float* out = (float*)d_out;

    static bool attr_set = false;
    if (!attr_set) {
        cudaFuncSetAttribute(k_conv1_fused,
                             cudaFuncAttributeMaxDynamicSharedMemorySize, SM_BYTES);
        attr_set = true;
    }

    dim3 g1(1, H, N);
    k_conv1_fused<<<g1, 256, SM_BYTES>>>(feat, wgt, w1, b1, w2, b2, bbuf);

    dim3 g3(HW / 128, K768 / 128, N);
    k_vgemm<<<g3, 256>>>(coef, feat);

    dim3 g4((N * HW) / 256, 8);
    k_combine<<<g4, 256>>>(bias, out);
}

// round 6
// speedup vs baseline: 1.5816x; 1.1566x over previous
#include <cuda_runtime.h>
#include <math.h>

typedef unsigned long long u64;

__device__ __forceinline__ u64 pack2(float lo, float hi) {
    u64 r; asm("mov.b64 %0, {%1, %2};" : "=l"(r) : "f"(lo), "f"(hi)); return r;
}
__device__ __forceinline__ void ffma2(u64& d, u64 a, u64 b) {
    asm("fma.rn.f32x2 %0, %1, %2, %3;" : "=l"(d) : "l"(a), "l"(b), "l"(d));
}
__device__ __forceinline__ float2 unpack2(u64 v) {
    float2 r; asm("mov.b64 {%0, %1}, %2;" : "=f"(r.x), "=f"(r.y) : "l"(v)); return r;
}
__device__ __forceinline__ unsigned smem_u32(const void* p) {
    unsigned a;
    asm("{ .reg .u64 t; cvta.to.shared.u64 t, %1; cvt.u32.u64 %0, t; }" : "=r"(a) : "l"(p));
    return a;
}
__device__ __forceinline__ void cp4(unsigned dst, const float* src, bool valid) {
    asm volatile("cp.async.ca.shared.global [%0], [%1], 4, %2;"
                 :: "r"(dst), "l"(src), "r"(valid ? 4 : 0));
}
__device__ __forceinline__ void cp16(unsigned dst, const float* src) {
    asm volatile("cp.async.cg.shared.global [%0], [%1], 16;" :: "r"(dst), "l"(src));
}
__device__ __forceinline__ void cp_commit() { asm volatile("cp.async.commit_group;"); }
template <int Nw>
__device__ __forceinline__ void cp_wait() { asm volatile("cp.async.wait_group %0;" :: "n"(Nw)); }

// Problem constants
constexpr int N   = 8;
constexpr int C   = 128;
constexpr int CW  = 64;
constexpr int CIN = C + CW;   // 192
constexpr int H   = 96;
constexpr int W   = 96;
constexpr int HW  = H * W;    // 9216
constexpr int K768 = C * 6;   // 768

// Static scratch
__device__ float g_bases[N * 54 * HW];            // 15.9 MB
__device__ float g_v    [(size_t)N * K768 * HW];  // 226.5 MB

// conv1_fused smem layout (floats)
// double buffers: buf b at [b*5952]: sIn(1200) + sW(4752)
// post-mainloop (aliases buffers): sW2(4608)@0, sBv(3552)@4608, sBB(54)@8160
// sH(12416)@11904
constexpr int SM_BUF  = 5952;
constexpr int SM_W2o  = 0;
constexpr int SM_BVo  = 4608;
constexpr int SM_BBo  = 8160;
constexpr int SM_Ho   = 11904;
constexpr int SM_TOT  = 24320;
constexpr int SM_BYTES = SM_TOT * 4;  // 97280 B

// ---------------------------------------------------------------------------
// Kernel 1: conv1(3x3,192->128)+tanh FUSED with conv2(1x1,128->36)+tanh and
// FB-basis combine. 512 threads, cp.async double-buffered mainloop.
// ---------------------------------------------------------------------------
__global__ __launch_bounds__(512, 2) void k_conv1_fused(
    const float* __restrict__ feat, const float* __restrict__ wgt,
    const float* __restrict__ w1,   const float* __restrict__ b1,
    const float* __restrict__ w2,   const float* __restrict__ b2,
    const float* __restrict__ bbuf)
{
    extern __shared__ float smem[];

    const int n = blockIdx.z;
    const int y = blockIdx.y;
    const int tid = threadIdx.x;
    const int tx  = tid & 15;      // 16 x-groups of 6 px
    const int tco = tid >> 4;      // 32 co-groups of 4 co
    const int x0  = tx * 6;
    const int co0 = tco * 4;

    u64 acc2[2][6];
    #pragma unroll
    for (int i = 0; i < 2; i++)
        #pragma unroll
        for (int j = 0; j < 6; j++) acc2[i][j] = 0ULL;

    // stage chunk cc (4 ci) into buffer b via cp.async
    auto stage = [&](int cc, int b) {
        float* sIn = smem + b * SM_BUF;
        float* sW  = smem + b * SM_BUF + 1200;
        // inputs: 4 ci x 3 rows x 98 cols (zero-padded)
        for (int i = tid; i < 4 * 3 * 98; i += 512) {
            int cil = i / 294;
            int rem = i - cil * 294;
            int r   = rem / 98;
            int xx  = rem - r * 98;
            int gy  = y + r - 1;
            int gx  = xx - 1;
            bool ok = (gy >= 0 && gy < H && gx >= 0 && gx < W);
            int ci = cc + cil;
            const float* src = (ci < C)
                ? &feat[((n * C + ci) * H + gy) * W + gx]
                : &wgt [((n * CW + (ci - C)) * H + gy) * W + gx];
            cp4(smem_u32(&sIn[(cil * 3 + r) * 100 + xx]), ok ? src : feat, ok);
        }
        // weights: 4 ci x 9 k x 128 co -> [cil*9+k][co] stride 132
        #pragma unroll
        for (int it = 0; it < 9; it++) {
            int i  = tid + it * 512;
            int co  = i / 36;
            int rem = i - co * 36;
            int cil = rem / 9;
            int k   = rem - cil * 9;
            cp4(smem_u32(&sW[(cil * 9 + k) * 132 + co]),
                &w1[(co * CIN + cc + cil) * 9 + k], true);
        }
    };

    stage(0, 0);
    cp_commit();

    constexpr int NCH = CIN / 4;   // 48
    for (int it = 0; it < NCH; it++) {
        const int cb = it & 1;
        __syncthreads();   // buffer cb^1 free to overwrite
        if (it + 1 < NCH) { stage((it + 1) * 4, cb ^ 1); cp_commit(); cp_wait<1>(); }
        else              { cp_wait<0>(); }
        __syncthreads();   // buffer cb visible

        const float* sIn = smem + cb * SM_BUF;
        const float* sW  = smem + cb * SM_BUF + 1200;

        #pragma unroll
        for (int cil = 0; cil < 4; cil++) {
            #pragma unroll
            for (int ky = 0; ky < 3; ky++) {
                const float* rowp = &sIn[(cil * 3 + ky) * 100];
                u64 bp[8];
                #pragma unroll
                for (int v = 0; v < 8; v++) {
                    float t = rowp[x0 + v];
                    bp[v] = pack2(t, t);
                }
                #pragma unroll
                for (int kx = 0; kx < 3; kx++) {
                    const int k = cil * 9 + ky * 3 + kx;
                    u64 a2[2];
                    #pragma unroll
                    for (int ip = 0; ip < 2; ip++)
                        a2[ip] = *reinterpret_cast<const u64*>(&sW[k * 132 + co0 + 2 * ip]);
                    #pragma unroll
                    for (int ip = 0; ip < 2; ip++)
                        #pragma unroll
                        for (int j = 0; j < 6; j++)
                            ffma2(acc2[ip][j], a2[ip], bp[kx + j]);
                }
            }
        }
    }

    // hmid -> sH (tanh applied)
    float* sH = smem + SM_Ho;
    #pragma unroll
    for (int ip = 0; ip < 2; ip++) {
        const float bb0 = b1[co0 + 2 * ip];
        const float bb1 = b1[co0 + 2 * ip + 1];
        #pragma unroll
        for (int j = 0; j < 6; j++) {
            float2 v = unpack2(acc2[ip][j]);
            sH[(co0 + 2 * ip)     * 97 + x0 + j] = tanhf(v.x + bb0);
            sH[(co0 + 2 * ip + 1) * 97 + x0 + j] = tanhf(v.y + bb1);
        }
    }
    __syncthreads();   // sH ready; buffers free for aliased reuse

    // preload W2 (transposed [ci][ch]) + FB bases into aliased region
    float* sW2 = smem + SM_W2o;
    float* sBv = smem + SM_BVo;
    float* sBB = smem + SM_BBo;
    #pragma unroll
    for (int itr = 0; itr < 9; itr++) {
        int i = tid + itr * 512;
        int ci = i / 36;
        int ch = i - ci * 36;
        sW2[i] = w2[ch * 128 + ci];
    }
    if (tid < 54) sBB[tid] = bbuf[tid];
    __syncthreads();

    // conv2: 4 threads per pixel, 9 channels each (384 active)
    if (tid < 384) {
        const int px  = tid >> 2;
        const int ch0 = (tid & 3) * 9;
        float a2c[9];
        #pragma unroll
        for (int q = 0; q < 9; q++) a2c[q] = 0.f;
        for (int ci = 0; ci < 128; ci++) {
            const float hv = sH[ci * 97 + px];
            const float* wr = &sW2[ci * 36 + ch0];
            #pragma unroll
            for (int q = 0; q < 9; q++)
                a2c[q] = fmaf(wr[q], hv, a2c[q]);
        }
        #pragma unroll
        for (int q = 0; q < 9; q++)
            sBv[px * 37 + ch0 + q] = tanhf(a2c[q] + b2[ch0 + q]);
    }
    __syncthreads();

    // FB-basis combine -> g_bases
    for (int i = tid; i < 54 * 96; i += 512) {
        const int j  = i / 96;
        const int px = i - j * 96;
        const int m  = j / 9;
        const int l  = j - m * 9;
        float s = 0.f;
        #pragma unroll
        for (int t = 0; t < 6; t++)
            s = fmaf(sBv[px * 37 + m * 6 + t], sBB[t * 9 + l], s);
        g_bases[(n * 54 + j) * HW + y * W + px] = s;
    }
}

// ---------------------------------------------------------------------------
// Kernel 2: V-GEMM with FFMA2 + cp.async double buffering.
// V[(c*6+m), p] = sum_{c'} coef[c, c'*6+m] * feat[c', p]
// ---------------------------------------------------------------------------
__global__ __launch_bounds__(256) void k_vgemm(
    const float* __restrict__ coef, const float* __restrict__ feat)
{
    const int n  = blockIdx.z;
    const int r0 = blockIdx.y * 128;
    const int p0 = blockIdx.x * 128;
    const int tid = threadIdx.x;
    const int tp = tid & 15;
    const int tc = tid >> 4;
    const int rr0 = tc * 8;
    const int pp0 = tp * 8;

    __shared__ float sA[2][16 * 132];
    __shared__ float sB[2][16 * 132];

    const float* Bp = feat + (size_t)n * C * HW + p0;

    u64 acc2[8][4];
    #pragma unroll
    for (int i = 0; i < 8; i++)
        #pragma unroll
        for (int j = 0; j < 4; j++) acc2[i][j] = 0ULL;

    auto stage = [&](int k0, int buf) {
        #pragma unroll
        for (int itr = 0; itr < 8; itr++) {
            int i  = tid + itr * 256;
            int kk = i >> 7;
            int row = i & 127;
            int rg = r0 + row;
            int c  = rg / 6;
            int m  = rg - c * 6;
            cp4(smem_u32(&sA[buf][kk * 132 + row]),
                &coef[c * K768 + (k0 + kk) * 6 + m], true);
        }
        #pragma unroll
        for (int itr = 0; itr < 2; itr++) {
            int i  = tid + itr * 256;
            int kk = i >> 5;
            int v  = i & 31;
            cp16(smem_u32(&sB[buf][kk * 132 + v * 4]),
                 &Bp[(size_t)(k0 + kk) * HW + v * 4]);
        }
    };

    stage(0, 0);
    cp_commit();

    #pragma unroll 1
    for (int iter = 0; iter < 8; iter++) {
        const int cb = iter & 1;
        __syncthreads();
        if (iter + 1 < 8) { stage((iter + 1) * 16, cb ^ 1); cp_commit(); cp_wait<1>(); }
        else              { cp_wait<0>(); }
        __syncthreads();

        #pragma unroll
        for (int kk = 0; kk < 16; kk++) {
            u64 ab[8], b2v[4];
            #pragma unroll
            for (int i = 0; i < 8; i++) {
                float a = sA[cb][kk * 132 + rr0 + i];
                ab[i] = pack2(a, a);
            }
            #pragma unroll
            for (int jp = 0; jp < 4; jp++)
                b2v[jp] = *reinterpret_cast<const u64*>(&sB[cb][kk * 132 + pp0 + 2 * jp]);
            #pragma unroll
            for (int i = 0; i < 8; i++)
                #pragma unroll
                for (int jp = 0; jp < 4; jp++)
                    ffma2(acc2[i][jp], ab[i], b2v[jp]);
        }
    }

    float* Vp = g_v + (size_t)n * K768 * HW + p0;
    #pragma unroll
    for (int i = 0; i < 8; i++) {
        float2 v0 = unpack2(acc2[i][0]);
        float2 v1 = unpack2(acc2[i][1]);
        float2 v2 = unpack2(acc2[i][2]);
        float2 v3 = unpack2(acc2[i][3]);
        *reinterpret_cast<float4*>(&Vp[(size_t)(r0 + rr0 + i) * HW + pp0]) =
            make_float4(v0.x, v0.y, v1.x, v1.y);
        *reinterpret_cast<float4*>(&Vp[(size_t)(r0 + rr0 + i) * HW + pp0 + 4]) =
            make_float4(v2.x, v2.y, v3.x, v3.y);
    }
}

// ---------------------------------------------------------------------------
// Kernel 3: combine (c-split).
// ---------------------------------------------------------------------------
__global__ __launch_bounds__(256) void k_combine(
    const float* __restrict__ bias, float* __restrict__ out)
{
    const int p  = blockIdx.x * 256 + threadIdx.x;
    const int cb = blockIdx.y * 16;
    const int n  = p / HW;
    const int hw = p - n * HW;
    const int y  = hw / W;
    const int x  = hw - y * W;

    float bs[6][9];
    #pragma unroll
    for (int m = 0; m < 6; m++)
        #pragma unroll
        for (int l = 0; l < 9; l++)
            bs[m][l] = __ldg(&g_bases[(n * 54 + m * 9 + l) * HW + hw]);

    int  off[9];
    #pragma unroll
    for (int l = 0; l < 9; l++) {
        const int dy = l / 3 - 1, dx = l % 3 - 1;
        off[l] = dy * W + dx;
        const bool ok = (unsigned)(y + dy) < (unsigned)H && (unsigned)(x + dx) < (unsigned)W;
        if (!ok) {
            #pragma unroll
            for (int m = 0; m < 6; m++) bs[m][l] = 0.f;
            off[l] = 0;
        }
    }

    const float* Vn = g_v + (size_t)n * K768 * HW + hw;
    float* on = out + (size_t)n * C * HW + hw;

    #pragma unroll 4
    for (int ci = 0; ci < 16; ci++) {
        const int c = cb + ci;
        float am[6];
        #pragma unroll
        for (int m = 0; m < 6; m++) {
            const float* row = Vn + (size_t)(c * 6 + m) * HW;
            float s = 0.f;
            #pragma unroll
            for (int l = 0; l < 9; l++)
                s = fmaf(bs[m][l], __ldg(row + off[l]), s);
            am[m] = s;
        }
        float r = ((am[0] + am[1]) + (am[2] + am[3])) + (am[4] + am[5]);
        on[(size_t)c * HW] = r + __ldg(&bias[c]);
    }
}

// ---------------------------------------------------------------------------
extern "C" void kernel_launch(void* const* d_in, const int* in_sizes, int n_in,
                              void* d_out, int out_size)
{
    const float* feat = (const float*)d_in[0];
    const float* wgt  = (const float*)d_in[1];
    const float* w1   = (const float*)d_in[2];
    const float* b1   = (const float*)d_in[3];
    const float* w2   = (const float*)d_in[4];
    const float* b2   = (const float*)d_in[5];
    const float* bbuf = (const float*)d_in[6];
    const float* coef = (const float*)d_in[7];
    const float* bias = (const float*)d_in[8];
    float* out = (float*)d_out;

    static bool attr_set = false;
    if (!attr_set) {
        cudaFuncSetAttribute(k_conv1_fused,
                             cudaFuncAttributeMaxDynamicSharedMemorySize, SM_BYTES);
        attr_set = true;
    }

    dim3 g1(1, H, N);
    k_conv1_fused<<<g1, 512, SM_BYTES>>>(feat, wgt, w1, b1, w2, b2, bbuf);

    dim3 g3(HW / 128, K768 / 128, N);
    k_vgemm<<<g3, 256>>>(coef, feat);

    dim3 g4((N * HW) / 256, 8);
    k_combine<<<g4, 256>>>(bias, out);
}

// round 8
// speedup vs baseline: 1.7791x; 1.1249x over previous
#include <cuda_runtime.h>
#include <cuda_bf16.h>
#include <math.h>

typedef unsigned long long u64;
typedef unsigned int u32;

__device__ __forceinline__ u64 pack2(float lo, float hi) {
    u64 r; asm("mov.b64 %0, {%1, %2};" : "=l"(r) : "f"(lo), "f"(hi)); return r;
}
__device__ __forceinline__ void ffma2(u64& d, u64 a, u64 b) {
    asm("fma.rn.f32x2 %0, %1, %2, %3;" : "=l"(d) : "l"(a), "l"(b), "l"(d));
}
__device__ __forceinline__ float2 unpack2(u64 v) {
    float2 r; asm("mov.b64 {%0, %1}, %2;" : "=f"(r.x), "=f"(r.y) : "l"(v)); return r;
}
__device__ __forceinline__ unsigned smem_u32p(const void* p) {
    unsigned a;
    asm("{ .reg .u64 t; cvta.to.shared.u64 t, %1; cvt.u32.u64 %0, t; }" : "=r"(a) : "l"(p));
    return a;
}
__device__ __forceinline__ void cp4(unsigned dst, const float* src, bool valid) {
    asm volatile("cp.async.ca.shared.global [%0], [%1], 4, %2;"
                 :: "r"(dst), "l"(src), "r"(valid ? 4 : 0));
}
__device__ __forceinline__ void cp_commit() { asm volatile("cp.async.commit_group;"); }
template <int Nw>
__device__ __forceinline__ void cp_wait() { asm volatile("cp.async.wait_group %0;" :: "n"(Nw)); }

// Problem constants
constexpr int N   = 8;
constexpr int C   = 128;
constexpr int CW  = 64;
constexpr int CIN = C + CW;   // 192
constexpr int H   = 96;
constexpr int W   = 96;
constexpr int HW  = H * W;    // 9216
constexpr int K768 = C * 6;   // 768

// Static scratch
__device__ float g_bases[N * 54 * HW];            // 15.9 MB
__device__ float g_v    [(size_t)N * K768 * HW];  // 226.5 MB
__device__ u32   g_ahi  [K768 * 64];              // coef^T split, hi bf16 pairs
__device__ u32   g_alo  [K768 * 64];              //               lo bf16 pairs

// ===========================================================================
// conv1_fused (unchanged from R6)
// ===========================================================================
constexpr int SM_BUF  = 5952;
constexpr int SM_W2o  = 0;
constexpr int SM_BVo  = 4608;
constexpr int SM_BBo  = 8160;
constexpr int SM_Ho   = 11904;
constexpr int SM_TOT  = 24320;
constexpr int SM_BYTES = SM_TOT * 4;  // 97280 B

__global__ __launch_bounds__(512, 2) void k_conv1_fused(
    const float* __restrict__ feat, const float* __restrict__ wgt,
    const float* __restrict__ w1,   const float* __restrict__ b1,
    const float* __restrict__ w2,   const float* __restrict__ b2,
    const float* __restrict__ bbuf)
{
    extern __shared__ float smem[];

    const int n = blockIdx.z;
    const int y = blockIdx.y;
    const int tid = threadIdx.x;
    const int tx  = tid & 15;
    const int tco = tid >> 4;
    const int x0  = tx * 6;
    const int co0 = tco * 4;

    u64 acc2[2][6];
    #pragma unroll
    for (int i = 0; i < 2; i++)
        #pragma unroll
        for (int j = 0; j < 6; j++) acc2[i][j] = 0ULL;

    auto stage = [&](int cc, int b) {
        float* sIn = smem + b * SM_BUF;
        float* sW  = smem + b * SM_BUF + 1200;
        for (int i = tid; i < 4 * 3 * 98; i += 512) {
            int cil = i / 294;
            int rem = i - cil * 294;
            int r   = rem / 98;
            int xx  = rem - r * 98;
            int gy  = y + r - 1;
            int gx  = xx - 1;
            bool ok = (gy >= 0 && gy < H && gx >= 0 && gx < W);
            int ci = cc + cil;
            const float* src = (ci < C)
                ? &feat[((n * C + ci) * H + gy) * W + gx]
                : &wgt [((n * CW + (ci - C)) * H + gy) * W + gx];
            cp4(smem_u32p(&sIn[(cil * 3 + r) * 100 + xx]), ok ? src : feat, ok);
        }
        #pragma unroll
        for (int it = 0; it < 9; it++) {
            int i  = tid + it * 512;
            int co  = i / 36;
            int rem = i - co * 36;
            int cil = rem / 9;
            int k   = rem - cil * 9;
            cp4(smem_u32p(&sW[(cil * 9 + k) * 132 + co]),
                &w1[(co * CIN + cc + cil) * 9 + k], true);
        }
    };

    stage(0, 0);
    cp_commit();

    constexpr int NCH = CIN / 4;   // 48
    for (int it = 0; it < NCH; it++) {
        const int cb = it & 1;
        __syncthreads();
        if (it + 1 < NCH) { stage((it + 1) * 4, cb ^ 1); cp_commit(); cp_wait<1>(); }
        else              { cp_wait<0>(); }
        __syncthreads();

        const float* sIn = smem + cb * SM_BUF;
        const float* sW  = smem + cb * SM_BUF + 1200;

        #pragma unroll
        for (int cil = 0; cil < 4; cil++) {
            #pragma unroll
            for (int ky = 0; ky < 3; ky++) {
                const float* rowp = &sIn[(cil * 3 + ky) * 100];
                u64 bp[8];
                #pragma unroll
                for (int v = 0; v < 8; v++) {
                    float t = rowp[x0 + v];
                    bp[v] = pack2(t, t);
                }
                #pragma unroll
                for (int kx = 0; kx < 3; kx++) {
                    const int k = cil * 9 + ky * 3 + kx;
                    u64 a2[2];
                    #pragma unroll
                    for (int ip = 0; ip < 2; ip++)
                        a2[ip] = *reinterpret_cast<const u64*>(&sW[k * 132 + co0 + 2 * ip]);
                    #pragma unroll
                    for (int ip = 0; ip < 2; ip++)
                        #pragma unroll
                        for (int j = 0; j < 6; j++)
                            ffma2(acc2[ip][j], a2[ip], bp[kx + j]);
                }
            }
        }
    }

    float* sH = smem + SM_Ho;
    #pragma unroll
    for (int ip = 0; ip < 2; ip++) {
        const float bb0 = b1[co0 + 2 * ip];
        const float bb1 = b1[co0 + 2 * ip + 1];
        #pragma unroll
        for (int j = 0; j < 6; j++) {
            float2 v = unpack2(acc2[ip][j]);
            sH[(co0 + 2 * ip)     * 97 + x0 + j] = tanhf(v.x + bb0);
            sH[(co0 + 2 * ip + 1) * 97 + x0 + j] = tanhf(v.y + bb1);
        }
    }
    __syncthreads();

    float* sW2 = smem + SM_W2o;
    float* sBv = smem + SM_BVo;
    float* sBB = smem + SM_BBo;
    #pragma unroll
    for (int itr = 0; itr < 9; itr++) {
        int i = tid + itr * 512;
        int ci = i / 36;
        int ch = i - ci * 36;
        sW2[i] = w2[ch * 128 + ci];
    }
    if (tid < 54) sBB[tid] = bbuf[tid];
    __syncthreads();

    if (tid < 384) {
        const int px  = tid >> 2;
        const int ch0 = (tid & 3) * 9;
        float a2c[9];
        #pragma unroll
        for (int q = 0; q < 9; q++) a2c[q] = 0.f;
        for (int ci = 0; ci < 128; ci++) {
            const float hv = sH[ci * 97 + px];
            const float* wr = &sW2[ci * 36 + ch0];
            #pragma unroll
            for (int q = 0; q < 9; q++)
                a2c[q] = fmaf(wr[q], hv, a2c[q]);
        }
        #pragma unroll
        for (int q = 0; q < 9; q++)
            sBv[px * 37 + ch0 + q] = tanhf(a2c[q] + b2[ch0 + q]);
    }
    __syncthreads();

    for (int i = tid; i < 54 * 96; i += 512) {
        const int j  = i / 96;
        const int px = i - j * 96;
        const int m  = j / 9;
        const int l  = j - m * 9;
        float s = 0.f;
        #pragma unroll
        for (int t = 0; t < 6; t++)
            s = fmaf(sBv[px * 37 + m * 6 + t], sBB[t * 9 + l], s);
        g_bases[(n * 54 + j) * HW + y * W + px] = s;
    }
}

// ===========================================================================
// bf16 split
// ===========================================================================
__device__ __forceinline__ void split2(float f0, float f1, u32& hi, u32& lo) {
    __nv_bfloat16 h0 = __float2bfloat16_rn(f0);
    __nv_bfloat16 h1 = __float2bfloat16_rn(f1);
    float l0f = f0 - __bfloat162float(h0);
    float l1f = f1 - __bfloat162float(h1);
    __nv_bfloat16 l0 = __float2bfloat16_rn(l0f);
    __nv_bfloat16 l1 = __float2bfloat16_rn(l1f);
    hi = ((u32)__bfloat16_as_ushort(h1) << 16) | (u32)__bfloat16_as_ushort(h0);
    lo = ((u32)__bfloat16_as_ushort(l1) << 16) | (u32)__bfloat16_as_ushort(l0);
}

// prep: coef^T split. A[rg][k] = coef[c*768 + k*6 + mm], rg = c*6+mm.
// g_a*[rg*64 + k2] = bf16 pair {A[rg][2k2], A[rg][2k2+1]}
__global__ __launch_bounds__(256) void k_prep_a(const float* __restrict__ coef)
{
    const int idx = blockIdx.x * 256 + threadIdx.x;
    const int rg = idx >> 6;
    const int k2 = idx & 63;
    const int c  = rg / 6;
    const int mm = rg - c * 6;
    const int k  = 2 * k2;
    float f0 = coef[c * K768 + k * 6 + mm];
    float f1 = coef[c * K768 + (k + 1) * 6 + mm];
    u32 hi, lo;
    split2(f0, f1, hi, lo);
    g_ahi[idx] = hi;
    g_alo[idx] = lo;
}

// ===========================================================================
// V-GEMM via mma.sync bf16 (fallback HMMA on sm_103).
// V[r0+m, p0+p] = sum_k A[r0+m][k] * feat[k][p0+p]
// Tile 128x128, K=128. 512 thr, 4x4 warps, warp tile 32x32.
// D += Ahi*Bhi + Ahi*Blo + Alo*Bhi  (fp32 accum, single pass).
// ===========================================================================
constexpr int PAD = 68;   // u32 stride; bank = (4*r + q) % 32 -> conflict-free frags

__device__ __forceinline__ void mma_bf16(float d[4], const u32 a[4], const u32 b[2]) {
    asm volatile(
        "mma.sync.aligned.m16n8k16.row.col.f32.bf16.bf16.f32 "
        "{%0,%1,%2,%3}, {%4,%5,%6,%7}, {%8,%9}, {%0,%1,%2,%3};"
        : "+f"(d[0]), "+f"(d[1]), "+f"(d[2]), "+f"(d[3])
        : "r"(a[0]), "r"(a[1]), "r"(a[2]), "r"(a[3]), "r"(b[0]), "r"(b[1]));
}

constexpr int VG_SMEM = 4 * 128 * PAD * 4;   // 139264 B

__global__ __launch_bounds__(512, 1) void k_vgemm_mma(const float* __restrict__ feat)
{
    extern __shared__ u32 vsm[];
    u32* sAhi = vsm;
    u32* sAlo = vsm + 128 * PAD;
    u32* sBhi = vsm + 2 * 128 * PAD;
    u32* sBlo = vsm + 3 * 128 * PAD;

    const int tid = threadIdx.x;
    const int n  = blockIdx.z;
    const int r0 = blockIdx.y * 128;
    const int p0 = blockIdx.x * 128;

    // stage A (already split): [m][k2]
    {
        const u32* ahi = &g_ahi[r0 * 64];
        const u32* alo = &g_alo[r0 * 64];
        #pragma unroll
        for (int it = 0; it < 16; it++) {
            int idx = tid + it * 512;
            int m  = idx >> 6;
            int k2 = idx & 63;
            sAhi[m * PAD + k2] = ahi[idx];
            sAlo[m * PAD + k2] = alo[idx];
        }
    }
    // stage B: split fp32 feat on the fly; sB[p][k2] pairs along k
    {
        const float* fB = feat + (size_t)n * C * HW + p0;
        #pragma unroll
        for (int it = 0; it < 16; it++) {
            int idx = tid + it * 512;
            int k2 = idx >> 7;
            int p  = idx & 127;
            float f0 = __ldg(&fB[(size_t)(2 * k2) * HW + p]);
            float f1 = __ldg(&fB[(size_t)(2 * k2 + 1) * HW + p]);
            u32 hi, lo;
            split2(f0, f1, hi, lo);
            sBhi[p * PAD + k2] = hi;
            sBlo[p * PAD + k2] = lo;
        }
    }
    __syncthreads();

    const int wid = tid >> 5;
    const int lane = tid & 31;
    const int wm = wid & 3;        // M32 group
    const int wn = wid >> 2;       // N32 group
    const int r  = lane >> 2;      // 0..7
    const int q  = lane & 3;       // 0..3

    float d[2][4][4];
    #pragma unroll
    for (int mi = 0; mi < 2; mi++)
        #pragma unroll
        for (int ni = 0; ni < 4; ni++)
            #pragma unroll
            for (int e = 0; e < 4; e++) d[mi][ni][e] = 0.f;

    #pragma unroll
    for (int ks = 0; ks < 8; ks++) {
        const int kc = ks * 8;
        u32 ahi[2][4], alo[2][4];
        #pragma unroll
        for (int mi = 0; mi < 2; mi++) {
            const int ra = wm * 32 + mi * 16 + r;
            ahi[mi][0] = sAhi[ra * PAD + kc + q];
            ahi[mi][1] = sAhi[(ra + 8) * PAD + kc + q];
            ahi[mi][2] = sAhi[ra * PAD + kc + 4 + q];
            ahi[mi][3] = sAhi[(ra + 8) * PAD + kc + 4 + q];
            alo[mi][0] = sAlo[ra * PAD + kc + q];
            alo[mi][1] = sAlo[(ra + 8) * PAD + kc + q];
            alo[mi][2] = sAlo[ra * PAD + kc + 4 + q];
            alo[mi][3] = sAlo[(ra + 8) * PAD + kc + 4 + q];
        }
        #pragma unroll
        for (int ni = 0; ni < 4; ni++) {
            const int nb = wn * 32 + ni * 8 + r;
            u32 bhi[2], blo[2];
            bhi[0] = sBhi[nb * PAD + kc + q];
            bhi[1] = sBhi[nb * PAD + kc + 4 + q];
            blo[0] = sBlo[nb * PAD + kc + q];
            blo[1] = sBlo[nb * PAD + kc + 4 + q];
            #pragma unroll
            for (int mi = 0; mi < 2; mi++) {
                mma_bf16(d[mi][ni], ahi[mi], bhi);
                mma_bf16(d[mi][ni], ahi[mi], blo);
                mma_bf16(d[mi][ni], alo[mi], bhi);
            }
        }
    }

    // epilogue: rows r0 + wm*32 + mi*16 + r (+8), cols p0 + wn*32 + ni*8 + 2q
    float* Vn = g_v + (size_t)n * K768 * HW;
    #pragma unroll
    for (int mi = 0; mi < 2; mi++) {
        const int row = r0 + wm * 32 + mi * 16 + r;
        #pragma unroll
        for (int ni = 0; ni < 4; ni++) {
            const int col = p0 + wn * 32 + ni * 8 + 2 * q;
            *reinterpret_cast<float2*>(&Vn[(size_t)row * HW + col]) =
                make_float2(d[mi][ni][0], d[mi][ni][1]);
            *reinterpret_cast<float2*>(&Vn[(size_t)(row + 8) * HW + col]) =
                make_float2(d[mi][ni][2], d[mi][ni][3]);
        }
    }
}

// ===========================================================================
// combine (c-split) -- unchanged
// ===========================================================================
__global__ __launch_bounds__(256) void k_combine(
    const float* __restrict__ bias, float* __restrict__ out)
{
    const int p  = blockIdx.x * 256 + threadIdx.x;
    const int cb = blockIdx.y * 16;
    const int n  = p / HW;
    const int hw = p - n * HW;
    const int y  = hw / W;
    const int x  = hw - y * W;

    float bs[6][9];
    #pragma unroll
    for (int m = 0; m < 6; m++)
        #pragma unroll
        for (int l = 0; l < 9; l++)
            bs[m][l] = __ldg(&g_bases[(n * 54 + m * 9 + l) * HW + hw]);

    int  off[9];
    #pragma unroll
    for (int l = 0; l < 9; l++) {
        const int dy = l / 3 - 1, dx = l % 3 - 1;
        off[l] = dy * W + dx;
        const bool ok = (unsigned)(y + dy) < (unsigned)H && (unsigned)(x + dx) < (unsigned)W;
        if (!ok) {
            #pragma unroll
            for (int m = 0; m < 6; m++) bs[m][l] = 0.f;
            off[l] = 0;
        }
    }

    const float* Vn = g_v + (size_t)n * K768 * HW + hw;
    float* on = out + (size_t)n * C * HW + hw;

    #pragma unroll 4
    for (int ci = 0; ci < 16; ci++) {
        const int c = cb + ci;
        float am[6];
        #pragma unroll
        for (int m = 0; m < 6; m++) {
            const float* row = Vn + (size_t)(c * 6 + m) * HW;
            float s = 0.f;
            #pragma unroll
            for (int l = 0; l < 9; l++)
                s = fmaf(bs[m][l], __ldg(row + off[l]), s);
            am[m] = s;
        }
        float r = ((am[0] + am[1]) + (am[2] + am[3])) + (am[4] + am[5]);
        on[(size_t)c * HW] = r + __ldg(&bias[c]);
    }
}

// ---------------------------------------------------------------------------
extern "C" void kernel_launch(void* const* d_in, const int* in_sizes, int n_in,
                              void* d_out, int out_size)
{
    const float* feat = (const float*)d_in[0];
    const float* wgt  = (const float*)d_in[1];
    const float* w1   = (const float*)d_in[2];
    const float* b1   = (const float*)d_in[3];
    const float* w2   = (const float*)d_in[4];
    const float* b2   = (const float*)d_in[5];
    const float* bbuf = (const float*)d_in[6];
    const float* coef = (const float*)d_in[7];
    const float* bias = (const float*)d_in[8];
    float* out = (float*)d_out;

    static bool attr_set = false;
    if (!attr_set) {
        cudaFuncSetAttribute(k_conv1_fused,
                             cudaFuncAttributeMaxDynamicSharedMemorySize, SM_BYTES);
        cudaFuncSetAttribute(k_vgemm_mma,
                             cudaFuncAttributeMaxDynamicSharedMemorySize, VG_SMEM);
        attr_set = true;
    }

    dim3 g1(1, H, N);
    k_conv1_fused<<<g1, 512, SM_BYTES>>>(feat, wgt, w1, b1, w2, b2, bbuf);

    k_prep_a<<<(K768 * 64) / 256, 256>>>(coef);

    dim3 g3(HW / 128, K768 / 128, N);
    k_vgemm_mma<<<g3, 512, VG_SMEM>>>(feat);

    dim3 g4((N * HW) / 256, 8);
    k_combine<<<g4, 256>>>(bias, out);
}

// round 9
// speedup vs baseline: 2.5079x; 1.4097x over previous
#include <cuda_runtime.h>
#include <cuda_bf16.h>
#include <math.h>

typedef unsigned long long u64;
typedef unsigned int u32;

__device__ __forceinline__ unsigned smem_u32p(const void* p) {
    unsigned a;
    asm("{ .reg .u64 t; cvta.to.shared.u64 t, %1; cvt.u32.u64 %0, t; }" : "=r"(a) : "l"(p));
    return a;
}
__device__ __forceinline__ void cp16(unsigned dst, const void* src) {
    asm volatile("cp.async.cg.shared.global [%0], [%1], 16;" :: "r"(dst), "l"(src));
}
__device__ __forceinline__ void cp_commit() { asm volatile("cp.async.commit_group;"); }
template <int Nw>
__device__ __forceinline__ void cp_wait() { asm volatile("cp.async.wait_group %0;" :: "n"(Nw)); }

// Problem constants
constexpr int N   = 8;
constexpr int C   = 128;
constexpr int CW  = 64;
constexpr int CIN = C + CW;   // 192
constexpr int H   = 96;
constexpr int W   = 96;
constexpr int HW  = H * W;    // 9216
constexpr int K768 = C * 6;   // 768

// Static scratch
__device__ float g_bases[N * 54 * HW];                    // 15.9 MB
__device__ float g_v    [(size_t)N * K768 * HW];          // 226.5 MB
__device__ __align__(16) u32 g_ahi [K768 * 64];           // coef^T split (vgemm A)
__device__ __align__(16) u32 g_alo [K768 * 64];
__device__ __align__(16) u32 g_w1hi[9 * 96 * 128];        // conv1 W split: [tap][ci2][co]
__device__ __align__(16) u32 g_w1lo[9 * 96 * 128];

// ===========================================================================
// bf16 split helper
// ===========================================================================
__device__ __forceinline__ void split2(float f0, float f1, u32& hi, u32& lo) {
    __nv_bfloat16 h0 = __float2bfloat16_rn(f0);
    __nv_bfloat16 h1 = __float2bfloat16_rn(f1);
    float l0f = f0 - __bfloat162float(h0);
    float l1f = f1 - __bfloat162float(h1);
    __nv_bfloat16 l0 = __float2bfloat16_rn(l0f);
    __nv_bfloat16 l1 = __float2bfloat16_rn(l1f);
    hi = ((u32)__bfloat16_as_ushort(h1) << 16) | (u32)__bfloat16_as_ushort(h0);
    lo = ((u32)__bfloat16_as_ushort(l1) << 16) | (u32)__bfloat16_as_ushort(l0);
}

__device__ __forceinline__ void mma_bf16(float d[4], const u32 a[4], u32 b0, u32 b1) {
    asm volatile(
        "mma.sync.aligned.m16n8k16.row.col.f32.bf16.bf16.f32 "
        "{%0,%1,%2,%3}, {%4,%5,%6,%7}, {%8,%9}, {%0,%1,%2,%3};"
        : "+f"(d[0]), "+f"(d[1]), "+f"(d[2]), "+f"(d[3])
        : "r"(a[0]), "r"(a[1]), "r"(a[2]), "r"(a[3]), "r"(b0), "r"(b1));
}

// ===========================================================================
// prep kernels
// ===========================================================================
// vgemm A: A[rg][k] = coef[c*768 + k*6 + mm], rg=c*6+mm; pairs along k.
__global__ __launch_bounds__(256) void k_prep_a(const float* __restrict__ coef)
{
    const int idx = blockIdx.x * 256 + threadIdx.x;
    const int rg = idx >> 6;
    const int k2 = idx & 63;
    const int c  = rg / 6;
    const int mm = rg - c * 6;
    const int k  = 2 * k2;
    u32 hi, lo;
    split2(coef[c * K768 + k * 6 + mm], coef[c * K768 + (k + 1) * 6 + mm], hi, lo);
    g_ahi[idx] = hi;
    g_alo[idx] = lo;
}

// conv1 W: g_w1hi[(tap*96+ci2)*128+co] = pair{w1[co][2ci2][tap], w1[co][2ci2+1][tap]}
__global__ __launch_bounds__(512) void k_prep_w1(const float* __restrict__ w1)
{
    const int idx = blockIdx.x * 512 + threadIdx.x;   // [0, 9*96*128)
    const int tap = idx / (96 * 128);
    const int rem = idx - tap * 96 * 128;
    const int ci2 = rem >> 7;
    const int co  = rem & 127;
    const float f0 = w1[(co * CIN + 2 * ci2)     * 9 + tap];
    const float f1 = w1[(co * CIN + 2 * ci2 + 1) * 9 + tap];
    u32 hi, lo;
    split2(f0, f1, hi, lo);
    g_w1hi[idx] = hi;
    g_w1lo[idx] = lo;
}

// ===========================================================================
// conv1 via mma.sync (implicit GEMM) fused with conv2 + FB bases.
// Block = (n, y): 128 co x 96 px, K = 192ci x 9taps. 512 threads, 16 warps 4x4.
// Warp tile 32co x 24px. D += Ahi*Bhi + Ahi*Blo + Alo*Bhi (fp32 accum).
// ===========================================================================
constexpr int CISTR = 328;                 // u32 stride per ci2 in input arrays (mod 32 == 8)
constexpr int IN_HI = 0;                   // 24 * 328 = 7872
constexpr int IN_LO = 7872;
constexpr int AB    = 15744;               // A tiles base
constexpr int ASTR  = 136;                 // u32 per ci2 row in A tile (mod 32 == 8)
constexpr int ATILE = 24 * ASTR;           // 3264
constexpr int SM_U32  = AB + 4 * ATILE;    // 28800 u32
constexpr int SM_BYTES = SM_U32 * 4;       // 115200 B

__global__ __launch_bounds__(512, 1) void k_conv1_mma(
    const float* __restrict__ feat, const float* __restrict__ wgt,
    const float* __restrict__ b1,
    const float* __restrict__ w2,   const float* __restrict__ b2,
    const float* __restrict__ bbuf)
{
    extern __shared__ u32 sm[];
    const int tid  = threadIdx.x;
    const int wid  = tid >> 5;
    const int lane = tid & 31;
    const int wm = wid & 3;          // co group (32 each)
    const int wn = wid >> 2;         // px group (24 each)
    const int r  = lane >> 2;        // 0..7
    const int q  = lane & 3;         // 0..3

    const int n = blockIdx.z;
    const int y = blockIdx.y;

    float d[2][3][4];
    #pragma unroll
    for (int mi = 0; mi < 2; mi++)
        #pragma unroll
        for (int ni = 0; ni < 3; ni++)
            #pragma unroll
            for (int e = 0; e < 4; e++) d[mi][ni][e] = 0.f;

    // stage A tile (tap, cg) into buffer buf via cp.async
    auto stageA = [&](int tap, int cg, int buf) {
        const u32* srcH = g_w1hi + (tap * 96 + cg * 24) * 128;
        const u32* srcL = g_w1lo + (tap * 96 + cg * 24) * 128;
        u32* dH = sm + AB + buf * 2 * ATILE;
        u32* dL = dH + ATILE;
        #pragma unroll
        for (int it = 0; it < 2; it++) {
            int i = tid + it * 512;            // [0,768): 24 ci2 x 32 float4
            if (i < 768) {
                int ci2l = i >> 5;
                int c4   = (i & 31) * 4;
                cp16(smem_u32p(&dH[ci2l * ASTR + c4]), &srcH[ci2l * 128 + c4]);
                cp16(smem_u32p(&dL[ci2l * ASTR + c4]), &srcL[ci2l * 128 + c4]);
            }
        }
    };

    // stage input group cg: 24 ci2 x 3 rows x 98 cols, split+packed
    auto stageIn = [&](int cg) {
        for (int i = tid; i < 24 * 294; i += 512) {
            int ci2l = i / 294;
            int rem  = i - ci2l * 294;
            int rr   = rem / 98;
            int xx   = rem - rr * 98;
            int gy   = y + rr - 1;
            int gx   = xx - 1;
            int ci   = cg * 48 + 2 * ci2l;
            float f0 = 0.f, f1 = 0.f;
            if (gy >= 0 && gy < H && gx >= 0 && gx < W) {
                const float* base = (ci < C)
                    ? &feat[((n * C + ci) * H + gy) * W + gx]
                    : &wgt [((n * CW + (ci - C)) * H + gy) * W + gx];
                f0 = base[0];
                f1 = base[HW];
            }
            u32 hi, lo;
            split2(f0, f1, hi, lo);
            sm[IN_HI + ci2l * CISTR + rr * 100 + xx] = hi;
            sm[IN_LO + ci2l * CISTR + rr * 100 + xx] = lo;
        }
    };

    stageA(0, 0, 0);
    cp_commit();

    int it = 0;
    for (int cg = 0; cg < 4; cg++) {
        __syncthreads();           // previous compute done; input buffer free
        stageIn(cg);
        for (int tap = 0; tap < 9; tap++, it++) {
            const int buf = it & 1;
            __syncthreads();       // all warps done with buf^1 (and input staged)
            if (it + 1 < 36) {
                const int nit = it + 1;
                stageA(nit % 9, nit / 9, buf ^ 1);
                cp_commit();
                cp_wait<1>();
            } else {
                cp_wait<0>();
            }
            __syncthreads();       // A(it) visible to all

            const int ky = tap / 3, kx = tap % 3;
            const u32* AH = sm + AB + buf * 2 * ATILE;
            const u32* AL = AH + ATILE;
            const int boff = ky * 100 + kx;

            #pragma unroll
            for (int s = 0; s < 3; s++) {
                const int kb2 = s * 8;
                u32 ahi[2][4], alo[2][4];
                #pragma unroll
                for (int mi = 0; mi < 2; mi++) {
                    const int ra = wm * 32 + mi * 16 + r;
                    ahi[mi][0] = AH[(kb2 + q) * ASTR + ra];
                    ahi[mi][1] = AH[(kb2 + q) * ASTR + ra + 8];
                    ahi[mi][2] = AH[(kb2 + 4 + q) * ASTR + ra];
                    ahi[mi][3] = AH[(kb2 + 4 + q) * ASTR + ra + 8];
                    alo[mi][0] = AL[(kb2 + q) * ASTR + ra];
                    alo[mi][1] = AL[(kb2 + q) * ASTR + ra + 8];
                    alo[mi][2] = AL[(kb2 + 4 + q) * ASTR + ra];
                    alo[mi][3] = AL[(kb2 + 4 + q) * ASTR + ra + 8];
                }
                #pragma unroll
                for (int ni = 0; ni < 3; ni++) {
                    const int px = wn * 24 + ni * 8 + r;
                    const int a0 = (kb2 + q) * CISTR + boff + px;
                    const int a1 = (kb2 + 4 + q) * CISTR + boff + px;
                    const u32 bhi0 = sm[IN_HI + a0];
                    const u32 bhi1 = sm[IN_HI + a1];
                    const u32 blo0 = sm[IN_LO + a0];
                    const u32 blo1 = sm[IN_LO + a1];
                    #pragma unroll
                    for (int mi = 0; mi < 2; mi++) {
                        mma_bf16(d[mi][ni], ahi[mi], bhi0, bhi1);
                        mma_bf16(d[mi][ni], ahi[mi], blo0, blo1);
                        mma_bf16(d[mi][ni], alo[mi], bhi0, bhi1);
                    }
                }
            }
        }
    }
    __syncthreads();   // mainloop done; smem free for aliasing

    // epilogue: hmid = tanh(D + b1) -> sH [co][97]
    float* sH = reinterpret_cast<float*>(sm);          // 128*97 = 12416 floats
    #pragma unroll
    for (int mi = 0; mi < 2; mi++) {
        const int row = wm * 32 + mi * 16 + r;
        const float bb0 = b1[row];
        const float bb1 = b1[row + 8];
        #pragma unroll
        for (int ni = 0; ni < 3; ni++) {
            const int col = wn * 24 + ni * 8 + 2 * q;
            sH[row * 97 + col]           = tanhf(d[mi][ni][0] + bb0);
            sH[row * 97 + col + 1]       = tanhf(d[mi][ni][1] + bb0);
            sH[(row + 8) * 97 + col]     = tanhf(d[mi][ni][2] + bb1);
            sH[(row + 8) * 97 + col + 1] = tanhf(d[mi][ni][3] + bb1);
        }
    }
    __syncthreads();

    // conv2 weights + FB bases into aliased A region
    float* sW2 = reinterpret_cast<float*>(sm + AB);            // 128*36
    float* sBv = reinterpret_cast<float*>(sm + AB) + 4608;     // 96*37
    float* sBB = reinterpret_cast<float*>(sm + AB) + 8160;     // 54
    #pragma unroll
    for (int itr = 0; itr < 9; itr++) {
        int i = tid + itr * 512;
        int ci = i / 36;
        int ch = i - ci * 36;
        sW2[i] = w2[ch * 128 + ci];
    }
    if (tid < 54) sBB[tid] = bbuf[tid];
    __syncthreads();

    // conv2: 4 threads per pixel, 9 channels each (384 active)
    if (tid < 384) {
        const int px  = tid >> 2;
        const int ch0 = (tid & 3) * 9;
        float a2c[9];
        #pragma unroll
        for (int qq = 0; qq < 9; qq++) a2c[qq] = 0.f;
        for (int ci = 0; ci < 128; ci++) {
            const float hv = sH[ci * 97 + px];
            const float* wr = &sW2[ci * 36 + ch0];
            #pragma unroll
            for (int qq = 0; qq < 9; qq++)
                a2c[qq] = fmaf(wr[qq], hv, a2c[qq]);
        }
        #pragma unroll
        for (int qq = 0; qq < 9; qq++)
            sBv[px * 37 + ch0 + qq] = tanhf(a2c[qq] + b2[ch0 + qq]);
    }
    __syncthreads();

    // FB-basis combine -> g_bases
    for (int i = tid; i < 54 * 96; i += 512) {
        const int j  = i / 96;
        const int px = i - j * 96;
        const int m  = j / 9;
        const int l  = j - m * 9;
        float s = 0.f;
        #pragma unroll
        for (int t = 0; t < 6; t++)
            s = fmaf(sBv[px * 37 + m * 6 + t], sBB[t * 9 + l], s);
        g_bases[(n * 54 + j) * HW + y * W + px] = s;
    }
}

// ===========================================================================
// V-GEMM via mma.sync bf16 (unchanged from R8)
// ===========================================================================
constexpr int PAD = 68;

constexpr int VG_SMEM = 4 * 128 * PAD * 4;   // 139264 B

__global__ __launch_bounds__(512, 1) void k_vgemm_mma(const float* __restrict__ feat)
{
    extern __shared__ u32 vsm[];
    u32* sAhi = vsm;
    u32* sAlo = vsm + 128 * PAD;
    u32* sBhi = vsm + 2 * 128 * PAD;
    u32* sBlo = vsm + 3 * 128 * PAD;

    const int tid = threadIdx.x;
    const int n  = blockIdx.z;
    const int r0 = blockIdx.y * 128;
    const int p0 = blockIdx.x * 128;

    {
        const u32* ahi = &g_ahi[r0 * 64];
        const u32* alo = &g_alo[r0 * 64];
        #pragma unroll
        for (int it = 0; it < 16; it++) {
            int idx = tid + it * 512;
            int m  = idx >> 6;
            int k2 = idx & 63;
            sAhi[m * PAD + k2] = ahi[idx];
            sAlo[m * PAD + k2] = alo[idx];
        }
    }
    {
        const float* fB = feat + (size_t)n * C * HW + p0;
        #pragma unroll
        for (int it = 0; it < 16; it++) {
            int idx = tid + it * 512;
            int k2 = idx >> 7;
            int p  = idx & 127;
            float f0 = __ldg(&fB[(size_t)(2 * k2) * HW + p]);
            float f1 = __ldg(&fB[(size_t)(2 * k2 + 1) * HW + p]);
            u32 hi, lo;
            split2(f0, f1, hi, lo);
            sBhi[p * PAD + k2] = hi;
            sBlo[p * PAD + k2] = lo;
        }
    }
    __syncthreads();

    const int wid = tid >> 5;
    const int lane = tid & 31;
    const int wm = wid & 3;
    const int wn = wid >> 2;
    const int r  = lane >> 2;
    const int q  = lane & 3;

    float d[2][4][4];
    #pragma unroll
    for (int mi = 0; mi < 2; mi++)
        #pragma unroll
        for (int ni = 0; ni < 4; ni++)
            #pragma unroll
            for (int e = 0; e < 4; e++) d[mi][ni][e] = 0.f;

    #pragma unroll
    for (int ks = 0; ks < 8; ks++) {
        const int kc = ks * 8;
        u32 ahi[2][4], alo[2][4];
        #pragma unroll
        for (int mi = 0; mi < 2; mi++) {
            const int ra = wm * 32 + mi * 16 + r;
            ahi[mi][0] = sAhi[ra * PAD + kc + q];
            ahi[mi][1] = sAhi[(ra + 8) * PAD + kc + q];
            ahi[mi][2] = sAhi[ra * PAD + kc + 4 + q];
            ahi[mi][3] = sAhi[(ra + 8) * PAD + kc + 4 + q];
            alo[mi][0] = sAlo[ra * PAD + kc + q];
            alo[mi][1] = sAlo[(ra + 8) * PAD + kc + q];
            alo[mi][2] = sAlo[ra * PAD + kc + 4 + q];
            alo[mi][3] = sAlo[(ra + 8) * PAD + kc + 4 + q];
        }
        #pragma unroll
        for (int ni = 0; ni < 4; ni++) {
            const int nb = wn * 32 + ni * 8 + r;
            u32 bhi0 = sBhi[nb * PAD + kc + q];
            u32 bhi1 = sBhi[nb * PAD + kc + 4 + q];
            u32 blo0 = sBlo[nb * PAD + kc + q];
            u32 blo1 = sBlo[nb * PAD + kc + 4 + q];
            #pragma unroll
            for (int mi = 0; mi < 2; mi++) {
                mma_bf16(d[mi][ni], ahi[mi], bhi0, bhi1);
                mma_bf16(d[mi][ni], ahi[mi], blo0, blo1);
                mma_bf16(d[mi][ni], alo[mi], bhi0, bhi1);
            }
        }
    }

    float* Vn = g_v + (size_t)n * K768 * HW;
    #pragma unroll
    for (int mi = 0; mi < 2; mi++) {
        const int row = r0 + wm * 32 + mi * 16 + r;
        #pragma unroll
        for (int ni = 0; ni < 4; ni++) {
            const int col = p0 + wn * 32 + ni * 8 + 2 * q;
            *reinterpret_cast<float2*>(&Vn[(size_t)row * HW + col]) =
                make_float2(d[mi][ni][0], d[mi][ni][1]);
            *reinterpret_cast<float2*>(&Vn[(size_t)(row + 8) * HW + col]) =
                make_float2(d[mi][ni][2], d[mi][ni][3]);
        }
    }
}

// ===========================================================================
// combine (c-split) -- unchanged
// ===========================================================================
__global__ __launch_bounds__(256) void k_combine(
    const float* __restrict__ bias, float* __restrict__ out)
{
    const int p  = blockIdx.x * 256 + threadIdx.x;
    const int cb = blockIdx.y * 16;
    const int n  = p / HW;
    const int hw = p - n * HW;
    const int y  = hw / W;
    const int x  = hw - y * W;

    float bs[6][9];
    #pragma unroll
    for (int m = 0; m < 6; m++)
        #pragma unroll
        for (int l = 0; l < 9; l++)
            bs[m][l] = __ldg(&g_bases[(n * 54 + m * 9 + l) * HW + hw]);

    int  off[9];
    #pragma unroll
    for (int l = 0; l < 9; l++) {
        const int dy = l / 3 - 1, dx = l % 3 - 1;
        off[l] = dy * W + dx;
        const bool ok = (unsigned)(y + dy) < (unsigned)H && (unsigned)(x + dx) < (unsigned)W;
        if (!ok) {
            #pragma unroll
            for (int m = 0; m < 6; m++) bs[m][l] = 0.f;
            off[l] = 0;
        }
    }

    const float* Vn = g_v + (size_t)n * K768 * HW + hw;
    float* on = out + (size_t)n * C * HW + hw;

    #pragma unroll 4
    for (int ci = 0; ci < 16; ci++) {
        const int c = cb + ci;
        float am[6];
        #pragma unroll
        for (int m = 0; m < 6; m++) {
            const float* row = Vn + (size_t)(c * 6 + m) * HW;
            float s = 0.f;
            #pragma unroll
            for (int l = 0; l < 9; l++)
                s = fmaf(bs[m][l], __ldg(row + off[l]), s);
            am[m] = s;
        }
        float r = ((am[0] + am[1]) + (am[2] + am[3])) + (am[4] + am[5]);
        on[(size_t)c * HW] = r + __ldg(&bias[c]);
    }
}

// ---------------------------------------------------------------------------
extern "C" void kernel_launch(void* const* d_in, const int* in_sizes, int n_in,
                              void* d_out, int out_size)
{
    const float* feat = (const float*)d_in[0];
    const float* wgt  = (const float*)d_in[1];
    const float* w1   = (const float*)d_in[2];
    const float* b1   = (const float*)d_in[3];
    const float* w2   = (const float*)d_in[4];
    const float* b2   = (const float*)d_in[5];
    const float* bbuf = (const float*)d_in[6];
    const float* coef = (const float*)d_in[7];
    const float* bias = (const float*)d_in[8];
    float* out = (float*)d_out;

    static bool attr_set = false;
    if (!attr_set) {
        cudaFuncSetAttribute(k_conv1_mma,
                             cudaFuncAttributeMaxDynamicSharedMemorySize, SM_BYTES);
        cudaFuncSetAttribute(k_vgemm_mma,
                             cudaFuncAttributeMaxDynamicSharedMemorySize, VG_SMEM);
        attr_set = true;
    }

    k_prep_w1<<<(9 * 96 * 128) / 512, 512>>>(w1);
    k_prep_a<<<(K768 * 64) / 256, 256>>>(coef);

    dim3 g1(1, H, N);
    k_conv1_mma<<<g1, 512, SM_BYTES>>>(feat, wgt, b1, w2, b2, bbuf);

    dim3 g3(HW / 128, K768 / 128, N);
    k_vgemm_mma<<<g3, 512, VG_SMEM>>>(feat);

    dim3 g4((N * HW) / 256, 8);
    k_combine<<<g4, 256>>>(bias, out);
}

// round 10
// speedup vs baseline: 2.9499x; 1.1762x over previous
#include <cuda_runtime.h>
#include <cuda_bf16.h>
#include <math.h>

typedef unsigned long long u64;
typedef unsigned int u32;

__device__ __forceinline__ unsigned smem_u32p(const void* p) {
    unsigned a;
    asm("{ .reg .u64 t; cvta.to.shared.u64 t, %1; cvt.u32.u64 %0, t; }" : "=r"(a) : "l"(p));
    return a;
}
__device__ __forceinline__ void cp16(unsigned dst, const void* src) {
    asm volatile("cp.async.cg.shared.global [%0], [%1], 16;" :: "r"(dst), "l"(src));
}
__device__ __forceinline__ void cp_commit() { asm volatile("cp.async.commit_group;"); }
template <int Nw>
__device__ __forceinline__ void cp_wait() { asm volatile("cp.async.wait_group %0;" :: "n"(Nw)); }

// Problem constants
constexpr int N   = 8;
constexpr int C   = 128;
constexpr int CW  = 64;
constexpr int CIN = C + CW;   // 192
constexpr int H   = 96;
constexpr int W   = 96;
constexpr int HW  = H * W;    // 9216
constexpr int K768 = C * 6;   // 768

// Static scratch
__device__ float g_bases[N * 54 * HW];
__device__ float g_v    [(size_t)N * K768 * HW];
__device__ __align__(16) u32 g_ahi [K768 * 64];
__device__ __align__(16) u32 g_alo [K768 * 64];
__device__ __align__(16) u32 g_w1hi[9 * 96 * 128];
__device__ __align__(16) u32 g_w1lo[9 * 96 * 128];

// ===========================================================================
__device__ __forceinline__ void split2(float f0, float f1, u32& hi, u32& lo) {
    __nv_bfloat16 h0 = __float2bfloat16_rn(f0);
    __nv_bfloat16 h1 = __float2bfloat16_rn(f1);
    float l0f = f0 - __bfloat162float(h0);
    float l1f = f1 - __bfloat162float(h1);
    __nv_bfloat16 l0 = __float2bfloat16_rn(l0f);
    __nv_bfloat16 l1 = __float2bfloat16_rn(l1f);
    hi = ((u32)__bfloat16_as_ushort(h1) << 16) | (u32)__bfloat16_as_ushort(h0);
    lo = ((u32)__bfloat16_as_ushort(l1) << 16) | (u32)__bfloat16_as_ushort(l0);
}

__device__ __forceinline__ void mma_bf16(float d[4], const u32 a[4], u32 b0, u32 b1) {
    asm volatile(
        "mma.sync.aligned.m16n8k16.row.col.f32.bf16.bf16.f32 "
        "{%0,%1,%2,%3}, {%4,%5,%6,%7}, {%8,%9}, {%0,%1,%2,%3};"
        : "+f"(d[0]), "+f"(d[1]), "+f"(d[2]), "+f"(d[3])
        : "r"(a[0]), "r"(a[1]), "r"(a[2]), "r"(a[3]), "r"(b0), "r"(b1));
}

// ===========================================================================
// prep kernels
// ===========================================================================
__global__ __launch_bounds__(256) void k_prep_a(const float* __restrict__ coef)
{
    const int idx = blockIdx.x * 256 + threadIdx.x;
    const int rg = idx >> 6;
    const int k2 = idx & 63;
    const int c  = rg / 6;
    const int mm = rg - c * 6;
    const int k  = 2 * k2;
    u32 hi, lo;
    split2(coef[c * K768 + k * 6 + mm], coef[c * K768 + (k + 1) * 6 + mm], hi, lo);
    g_ahi[idx] = hi;
    g_alo[idx] = lo;
}

__global__ __launch_bounds__(512) void k_prep_w1(const float* __restrict__ w1)
{
    const int idx = blockIdx.x * 512 + threadIdx.x;
    const int tap = idx / (96 * 128);
    const int rem = idx - tap * 96 * 128;
    const int ci2 = rem >> 7;
    const int co  = rem & 127;
    const float f0 = w1[(co * CIN + 2 * ci2)     * 9 + tap];
    const float f1 = w1[(co * CIN + 2 * ci2 + 1) * 9 + tap];
    u32 hi, lo;
    split2(f0, f1, hi, lo);
    g_w1hi[idx] = hi;
    g_w1lo[idx] = lo;
}

// ===========================================================================
// conv1 mma v2: 2 image rows per block. 128 co x 192 px, K = 192ci x 9taps.
// 512 threads, 16 warps = 4 co-groups x 4 px-groups (48 px each).
// Warp tile 32co x 48px -> d[2][6][4]. 3-pass bf16 split.
// ===========================================================================
constexpr int CISTR = 424;                 // u32/ci2 (4 rows x 100 + pad); mod 32 == 8
constexpr int IN_HI = 0;                   // 24 * 424 = 10176
constexpr int IN_LO = 10176;
constexpr int AB    = 20352;
constexpr int ASTR  = 136;                 // mod 32 == 8
constexpr int ATILE = 24 * ASTR;           // 3264
constexpr int SM_MAIN = AB + 4 * ATILE;    // 33408 u32
// epilogue aliases: sH [128][194] @0 (24832), sW2 @24832 (4608), sBv @29440 (7104), sBB @36544 (64)
constexpr int SM_U32  = 36608 + 64;
constexpr int SM_BYTES = SM_U32 * 4;       // 146688 B

__global__ __launch_bounds__(512, 1) void k_conv1_mma(
    const float* __restrict__ feat, const float* __restrict__ wgt,
    const float* __restrict__ b1,
    const float* __restrict__ w2,   const float* __restrict__ b2,
    const float* __restrict__ bbuf)
{
    extern __shared__ u32 sm[];
    const int tid  = threadIdx.x;
    const int wid  = tid >> 5;
    const int lane = tid & 31;
    const int wm = wid & 3;          // co group (32)
    const int wn = wid >> 2;         // px group (48)
    const int r  = lane >> 2;
    const int q  = lane & 3;

    const int n  = blockIdx.z;
    const int y0 = blockIdx.y * 2;   // two output rows y0, y0+1

    float d[2][6][4];
    #pragma unroll
    for (int mi = 0; mi < 2; mi++)
        #pragma unroll
        for (int ni = 0; ni < 6; ni++)
            #pragma unroll
            for (int e = 0; e < 4; e++) d[mi][ni][e] = 0.f;

    auto stageA = [&](int tap, int cg, int buf) {
        const u32* srcH = g_w1hi + (tap * 96 + cg * 24) * 128;
        const u32* srcL = g_w1lo + (tap * 96 + cg * 24) * 128;
        u32* dH = sm + AB + buf * 2 * ATILE;
        u32* dL = dH + ATILE;
        #pragma unroll
        for (int it = 0; it < 2; it++) {
            int i = tid + it * 512;
            if (i < 768) {
                int ci2l = i >> 5;
                int c4   = (i & 31) * 4;
                cp16(smem_u32p(&dH[ci2l * ASTR + c4]), &srcH[ci2l * 128 + c4]);
                cp16(smem_u32p(&dL[ci2l * ASTR + c4]), &srcL[ci2l * 128 + c4]);
            }
        }
    };

    // stage inputs: 24 ci2 x 4 rows x 98 cols (rows y0-1 .. y0+2)
    auto stageIn = [&](int cg) {
        for (int i = tid; i < 24 * 4 * 98; i += 512) {
            int ci2l = i / 392;
            int rem  = i - ci2l * 392;
            int rr   = rem / 98;
            int xx   = rem - rr * 98;
            int gy   = y0 + rr - 1;
            int gx   = xx - 1;
            int ci   = cg * 48 + 2 * ci2l;
            float f0 = 0.f, f1 = 0.f;
            if (gy >= 0 && gy < H && gx >= 0 && gx < W) {
                const float* base = (ci < C)
                    ? &feat[((n * C + ci) * H + gy) * W + gx]
                    : &wgt [((n * CW + (ci - C)) * H + gy) * W + gx];
                f0 = base[0];
                f1 = base[HW];
            }
            u32 hi, lo;
            split2(f0, f1, hi, lo);
            sm[IN_HI + ci2l * CISTR + rr * 100 + xx] = hi;
            sm[IN_LO + ci2l * CISTR + rr * 100 + xx] = lo;
        }
    };

    stageA(0, 0, 0);
    cp_commit();

    const int prow = wn >> 1;                 // image row within pair (0/1)
    const int px0  = (wn & 1) * 48;           // x start of this warp's 48 px

    int it = 0;
    for (int cg = 0; cg < 4; cg++) {
        __syncthreads();
        stageIn(cg);
        for (int tap = 0; tap < 9; tap++, it++) {
            const int buf = it & 1;
            __syncthreads();
            if (it + 1 < 36) {
                const int nit = it + 1;
                stageA(nit % 9, nit / 9, buf ^ 1);
                cp_commit();
                cp_wait<1>();
            } else {
                cp_wait<0>();
            }
            __syncthreads();

            const int ky = tap / 3, kx = tap % 3;
            const u32* AH = sm + AB + buf * 2 * ATILE;
            const u32* AL = AH + ATILE;
            const int boff = (prow + ky) * 100 + kx + px0;

            #pragma unroll
            for (int s = 0; s < 3; s++) {
                const int kb2 = s * 8;
                u32 ahi[2][4], alo[2][4];
                #pragma unroll
                for (int mi = 0; mi < 2; mi++) {
                    const int ra = wm * 32 + mi * 16 + r;
                    ahi[mi][0] = AH[(kb2 + q) * ASTR + ra];
                    ahi[mi][1] = AH[(kb2 + q) * ASTR + ra + 8];
                    ahi[mi][2] = AH[(kb2 + 4 + q) * ASTR + ra];
                    ahi[mi][3] = AH[(kb2 + 4 + q) * ASTR + ra + 8];
                    alo[mi][0] = AL[(kb2 + q) * ASTR + ra];
                    alo[mi][1] = AL[(kb2 + q) * ASTR + ra + 8];
                    alo[mi][2] = AL[(kb2 + 4 + q) * ASTR + ra];
                    alo[mi][3] = AL[(kb2 + 4 + q) * ASTR + ra + 8];
                }
                #pragma unroll
                for (int ni = 0; ni < 6; ni++) {
                    const int a0 = (kb2 + q) * CISTR + boff + ni * 8 + r;
                    const int a1 = (kb2 + 4 + q) * CISTR + boff + ni * 8 + r;
                    const u32 bhi0 = sm[IN_HI + a0];
                    const u32 bhi1 = sm[IN_HI + a1];
                    const u32 blo0 = sm[IN_LO + a0];
                    const u32 blo1 = sm[IN_LO + a1];
                    #pragma unroll
                    for (int mi = 0; mi < 2; mi++) {
                        mma_bf16(d[mi][ni], ahi[mi], bhi0, bhi1);
                        mma_bf16(d[mi][ni], ahi[mi], blo0, blo1);
                        mma_bf16(d[mi][ni], alo[mi], bhi0, bhi1);
                    }
                }
            }
        }
    }
    __syncthreads();

    // epilogue: hmid = tanh(D + b1) -> sH [co][194], px = prow*96 + x
    float* sH = reinterpret_cast<float*>(sm);          // 128*194
    #pragma unroll
    for (int mi = 0; mi < 2; mi++) {
        const int row = wm * 32 + mi * 16 + r;
        const float bb0 = b1[row];
        const float bb1 = b1[row + 8];
        #pragma unroll
        for (int ni = 0; ni < 6; ni++) {
            const int px = prow * 96 + px0 + ni * 8 + 2 * q;
            sH[row * 194 + px]           = tanhf(d[mi][ni][0] + bb0);
            sH[row * 194 + px + 1]       = tanhf(d[mi][ni][1] + bb0);
            sH[(row + 8) * 194 + px]     = tanhf(d[mi][ni][2] + bb1);
            sH[(row + 8) * 194 + px + 1] = tanhf(d[mi][ni][3] + bb1);
        }
    }
    __syncthreads();

    float* sW2 = reinterpret_cast<float*>(sm) + 24832;   // 128*36
    float* sBv = reinterpret_cast<float*>(sm) + 29440;   // 192*37
    float* sBB = reinterpret_cast<float*>(sm) + 36544;   // 54
    #pragma unroll
    for (int itr = 0; itr < 9; itr++) {
        int i = tid + itr * 512;
        int ci = i / 36;
        int ch = i - ci * 36;
        sW2[i] = w2[ch * 128 + ci];
    }
    if (tid < 54) sBB[tid] = bbuf[tid];
    __syncthreads();

    // conv2: 2 threads per pixel (384 active), 18 channels each
    if (tid < 384) {
        const int px  = tid >> 1;            // 0..191
        const int ch0 = (tid & 1) * 18;
        float a2c[18];
        #pragma unroll
        for (int qq = 0; qq < 18; qq++) a2c[qq] = 0.f;
        for (int ci = 0; ci < 128; ci++) {
            const float hv = sH[ci * 194 + px];
            const float* wr = &sW2[ci * 36 + ch0];
            #pragma unroll
            for (int qq = 0; qq < 18; qq++)
                a2c[qq] = fmaf(wr[qq], hv, a2c[qq]);
        }
        #pragma unroll
        for (int qq = 0; qq < 18; qq++)
            sBv[px * 37 + ch0 + qq] = tanhf(a2c[qq] + b2[ch0 + qq]);
    }
    __syncthreads();

    // FB-basis combine -> g_bases (two rows)
    for (int i = tid; i < 54 * 192; i += 512) {
        const int j  = i / 192;
        const int px = i - j * 192;
        const int row = px / 96;
        const int x   = px - row * 96;
        const int m  = j / 9;
        const int l  = j - m * 9;
        float s = 0.f;
        #pragma unroll
        for (int t = 0; t < 6; t++)
            s = fmaf(sBv[px * 37 + m * 6 + t], sBB[t * 9 + l], s);
        g_bases[(n * 54 + j) * HW + (y0 + row) * W + x] = s;
    }
}

// ===========================================================================
// V-GEMM via mma.sync bf16 (unchanged)
// ===========================================================================
constexpr int PAD = 68;
constexpr int VG_SMEM = 4 * 128 * PAD * 4;

__global__ __launch_bounds__(512, 1) void k_vgemm_mma(const float* __restrict__ feat)
{
    extern __shared__ u32 vsm[];
    u32* sAhi = vsm;
    u32* sAlo = vsm + 128 * PAD;
    u32* sBhi = vsm + 2 * 128 * PAD;
    u32* sBlo = vsm + 3 * 128 * PAD;

    const int tid = threadIdx.x;
    const int n  = blockIdx.z;
    const int r0 = blockIdx.y * 128;
    const int p0 = blockIdx.x * 128;

    {
        const u32* ahi = &g_ahi[r0 * 64];
        const u32* alo = &g_alo[r0 * 64];
        #pragma unroll
        for (int it = 0; it < 16; it++) {
            int idx = tid + it * 512;
            int m  = idx >> 6;
            int k2 = idx & 63;
            sAhi[m * PAD + k2] = ahi[idx];
            sAlo[m * PAD + k2] = alo[idx];
        }
    }
    {
        const float* fB = feat + (size_t)n * C * HW + p0;
        #pragma unroll
        for (int it = 0; it < 16; it++) {
            int idx = tid + it * 512;
            int k2 = idx >> 7;
            int p  = idx & 127;
            float f0 = __ldg(&fB[(size_t)(2 * k2) * HW + p]);
            float f1 = __ldg(&fB[(size_t)(2 * k2 + 1) * HW + p]);
            u32 hi, lo;
            split2(f0, f1, hi, lo);
            sBhi[p * PAD + k2] = hi;
            sBlo[p * PAD + k2] = lo;
        }
    }
    __syncthreads();

    const int wid = tid >> 5;
    const int lane = tid & 31;
    const int wm = wid & 3;
    const int wn = wid >> 2;
    const int r  = lane >> 2;
    const int q  = lane & 3;

    float d[2][4][4];
    #pragma unroll
    for (int mi = 0; mi < 2; mi++)
        #pragma unroll
        for (int ni = 0; ni < 4; ni++)
            #pragma unroll
            for (int e = 0; e < 4; e++) d[mi][ni][e] = 0.f;

    #pragma unroll
    for (int ks = 0; ks < 8; ks++) {
        const int kc = ks * 8;
        u32 ahi[2][4], alo[2][4];
        #pragma unroll
        for (int mi = 0; mi < 2; mi++) {
            const int ra = wm * 32 + mi * 16 + r;
            ahi[mi][0] = sAhi[ra * PAD + kc + q];
            ahi[mi][1] = sAhi[(ra + 8) * PAD + kc + q];
            ahi[mi][2] = sAhi[ra * PAD + kc + 4 + q];
            ahi[mi][3] = sAhi[(ra + 8) * PAD + kc + 4 + q];
            alo[mi][0] = sAlo[ra * PAD + kc + q];
            alo[mi][1] = sAlo[(ra + 8) * PAD + kc + q];
            alo[mi][2] = sAlo[ra * PAD + kc + 4 + q];
            alo[mi][3] = sAlo[(ra + 8) * PAD + kc + 4 + q];
        }
        #pragma unroll
        for (int ni = 0; ni < 4; ni++) {
            const int nb = wn * 32 + ni * 8 + r;
            u32 bhi0 = sBhi[nb * PAD + kc + q];
            u32 bhi1 = sBhi[nb * PAD + kc + 4 + q];
            u32 blo0 = sBlo[nb * PAD + kc + q];
            u32 blo1 = sBlo[nb * PAD + kc + 4 + q];
            #pragma unroll
            for (int mi = 0; mi < 2; mi++) {
                mma_bf16(d[mi][ni], ahi[mi], bhi0, bhi1);
                mma_bf16(d[mi][ni], ahi[mi], blo0, blo1);
                mma_bf16(d[mi][ni], alo[mi], bhi0, bhi1);
            }
        }
    }

    float* Vn = g_v + (size_t)n * K768 * HW;
    #pragma unroll
    for (int mi = 0; mi < 2; mi++) {
        const int row = r0 + wm * 32 + mi * 16 + r;
        #pragma unroll
        for (int ni = 0; ni < 4; ni++) {
            const int col = p0 + wn * 32 + ni * 8 + 2 * q;
            *reinterpret_cast<float2*>(&Vn[(size_t)row * HW + col]) =
                make_float2(d[mi][ni][0], d[mi][ni][1]);
            *reinterpret_cast<float2*>(&Vn[(size_t)(row + 8) * HW + col]) =
                make_float2(d[mi][ni][2], d[mi][ni][3]);
        }
    }
}

// ===========================================================================
// combine v2: m-outer loop, 16 channels per block, low register pressure.
// ===========================================================================
__global__ __launch_bounds__(256) void k_combine(
    const float* __restrict__ bias, float* __restrict__ out)
{
    const int p  = blockIdx.x * 256 + threadIdx.x;
    const int cb = blockIdx.y * 16;
    const int n  = p / HW;
    const int hw = p - n * HW;
    const int y  = hw / W;
    const int x  = hw - y * W;

    int  off[9];
    u32  okm = 0;
    #pragma unroll
    for (int l = 0; l < 9; l++) {
        const int dy = l / 3 - 1, dx = l % 3 - 1;
        const bool ok = (unsigned)(y + dy) < (unsigned)H && (unsigned)(x + dx) < (unsigned)W;
        off[l] = ok ? (dy * W + dx) : 0;
        okm |= (ok ? 1u : 0u) << l;
    }

    float acc[16];
    #pragma unroll
    for (int ci = 0; ci < 16; ci++) acc[ci] = 0.f;

    const float* Vn = g_v + (size_t)n * K768 * HW + hw;

    #pragma unroll
    for (int m = 0; m < 6; m++) {
        float bs[9];
        #pragma unroll
        for (int l = 0; l < 9; l++) {
            float t = __ldg(&g_bases[(n * 54 + m * 9 + l) * HW + hw]);
            bs[l] = (okm >> l & 1u) ? t : 0.f;
        }
        const float* Vm = Vn + (size_t)(cb * 6 + m) * HW;
        #pragma unroll
        for (int ci = 0; ci < 16; ci++) {
            const float* row = Vm + (size_t)(ci * 6) * HW;
            float s = 0.f;
            #pragma unroll
            for (int l = 0; l < 9; l++)
                s = fmaf(bs[l], __ldg(row + off[l]), s);
            acc[ci] += s;
        }
    }

    float* on = out + (size_t)n * C * HW + hw;
    #pragma unroll
    for (int ci = 0; ci < 16; ci++)
        on[(size_t)(cb + ci) * HW] = acc[ci] + __ldg(&bias[cb + ci]);
}

// ---------------------------------------------------------------------------
extern "C" void kernel_launch(void* const* d_in, const int* in_sizes, int n_in,
                              void* d_out, int out_size)
{
    const float* feat = (const float*)d_in[0];
    const float* wgt  = (const float*)d_in[1];
    const float* w1   = (const float*)d_in[2];
    const float* b1   = (const float*)d_in[3];
    const float* w2   = (const float*)d_in[4];
    const float* b2   = (const float*)d_in[5];
    const float* bbuf = (const float*)d_in[6];
    const float* coef = (const float*)d_in[7];
    const float* bias = (const float*)d_in[8];
    float* out = (float*)d_out;

    static bool attr_set = false;
    if (!attr_set) {
        cudaFuncSetAttribute(k_conv1_mma,
                             cudaFuncAttributeMaxDynamicSharedMemorySize, SM_BYTES);
        cudaFuncSetAttribute(k_vgemm_mma,
                             cudaFuncAttributeMaxDynamicSharedMemorySize, VG_SMEM);
        attr_set = true;
    }

    k_prep_w1<<<(9 * 96 * 128) / 512, 512>>>(w1);
    k_prep_a<<<(K768 * 64) / 256, 256>>>(coef);

    dim3 g1(1, H / 2, N);
    k_conv1_mma<<<g1, 512, SM_BYTES>>>(feat, wgt, b1, w2, b2, bbuf);

    dim3 g3(HW / 128, K768 / 128, N);
    k_vgemm_mma<<<g3, 512, VG_SMEM>>>(feat);

    dim3 g4((N * HW) / 256, 8);
    k_combine<<<g4, 256>>>(bias, out);
}

// round 11
// speedup vs baseline: 3.1821x; 1.0787x over previous
#include <cuda_runtime.h>
#include <cuda_bf16.h>
#include <math.h>

typedef unsigned long long u64;
typedef unsigned int u32;

__device__ __forceinline__ unsigned smem_u32p(const void* p) {
    unsigned a;
    asm("{ .reg .u64 t; cvta.to.shared.u64 t, %1; cvt.u32.u64 %0, t; }" : "=r"(a) : "l"(p));
    return a;
}
__device__ __forceinline__ void cp16(unsigned dst, const void* src) {
    asm volatile("cp.async.cg.shared.global [%0], [%1], 16;" :: "r"(dst), "l"(src));
}
__device__ __forceinline__ void cp4(unsigned dst, const void* src) {
    asm volatile("cp.async.ca.shared.global [%0], [%1], 4;" :: "r"(dst), "l"(src));
}
__device__ __forceinline__ void cp_commit() { asm volatile("cp.async.commit_group;"); }
template <int Nw>
__device__ __forceinline__ void cp_wait() { asm volatile("cp.async.wait_group %0;" :: "n"(Nw)); }

// Problem constants
constexpr int N   = 8;
constexpr int C   = 128;
constexpr int CW  = 64;
constexpr int CIN = C + CW;   // 192
constexpr int H   = 96;
constexpr int W   = 96;
constexpr int HW  = H * W;    // 9216
constexpr int K768 = C * 6;   // 768

// Static scratch
__device__ float g_bases[N * 54 * HW];
__device__ float g_v    [(size_t)N * K768 * HW];
__device__ __align__(16) u32 g_ahi [K768 * 64];
__device__ __align__(16) u32 g_alo [K768 * 64];
__device__ __align__(16) u32 g_w1hi[9 * 96 * 128];
__device__ __align__(16) u32 g_w1lo[9 * 96 * 128];
// pre-split, pre-padded inputs: [n][96 ci2][98 rows][104 cols]
constexpr int IN_CI = 96;
constexpr int IN_R  = 98;
constexpr int IN_CSTR = 104;
constexpr int IN_NSTR = IN_CI * IN_R * IN_CSTR;   // 978432
__device__ __align__(16) u32 g_inhi[N * IN_NSTR];  // 31.3 MB
__device__ __align__(16) u32 g_inlo[N * IN_NSTR];

// ===========================================================================
__device__ __forceinline__ void split2(float f0, float f1, u32& hi, u32& lo) {
    __nv_bfloat16 h0 = __float2bfloat16_rn(f0);
    __nv_bfloat16 h1 = __float2bfloat16_rn(f1);
    float l0f = f0 - __bfloat162float(h0);
    float l1f = f1 - __bfloat162float(h1);
    __nv_bfloat16 l0 = __float2bfloat16_rn(l0f);
    __nv_bfloat16 l1 = __float2bfloat16_rn(l1f);
    hi = ((u32)__bfloat16_as_ushort(h1) << 16) | (u32)__bfloat16_as_ushort(h0);
    lo = ((u32)__bfloat16_as_ushort(l1) << 16) | (u32)__bfloat16_as_ushort(l0);
}

__device__ __forceinline__ void mma_bf16(float d[4], const u32 a[4], u32 b0, u32 b1) {
    asm volatile(
        "mma.sync.aligned.m16n8k16.row.col.f32.bf16.bf16.f32 "
        "{%0,%1,%2,%3}, {%4,%5,%6,%7}, {%8,%9}, {%0,%1,%2,%3};"
        : "+f"(d[0]), "+f"(d[1]), "+f"(d[2]), "+f"(d[3])
        : "r"(a[0]), "r"(a[1]), "r"(a[2]), "r"(a[3]), "r"(b0), "r"(b1));
}

// ===========================================================================
// prep kernels
// ===========================================================================
__global__ __launch_bounds__(256) void k_prep_a(const float* __restrict__ coef)
{
    const int idx = blockIdx.x * 256 + threadIdx.x;
    const int rg = idx >> 6;
    const int k2 = idx & 63;
    const int c  = rg / 6;
    const int mm = rg - c * 6;
    const int k  = 2 * k2;
    u32 hi, lo;
    split2(coef[c * K768 + k * 6 + mm], coef[c * K768 + (k + 1) * 6 + mm], hi, lo);
    g_ahi[idx] = hi;
    g_alo[idx] = lo;
}

__global__ __launch_bounds__(512) void k_prep_w1(const float* __restrict__ w1)
{
    const int idx = blockIdx.x * 512 + threadIdx.x;
    const int tap = idx / (96 * 128);
    const int rem = idx - tap * 96 * 128;
    const int ci2 = rem >> 7;
    const int co  = rem & 127;
    const float f0 = w1[(co * CIN + 2 * ci2)     * 9 + tap];
    const float f1 = w1[(co * CIN + 2 * ci2 + 1) * 9 + tap];
    u32 hi, lo;
    split2(f0, f1, hi, lo);
    g_w1hi[idx] = hi;
    g_w1lo[idx] = lo;
}

// split feat+wgt into padded pair arrays
__global__ __launch_bounds__(512) void k_prep_in(
    const float* __restrict__ feat, const float* __restrict__ wgt)
{
    const int idx = blockIdx.x * 512 + threadIdx.x;   // [0, N*IN_NSTR)
    const int n   = idx / IN_NSTR;
    int rem = idx - n * IN_NSTR;
    const int ci2 = rem / (IN_R * IN_CSTR);
    rem -= ci2 * (IN_R * IN_CSTR);
    const int row = rem / IN_CSTR;
    const int col = rem - row * IN_CSTR;
    float f0 = 0.f, f1 = 0.f;
    if (row >= 1 && row <= 96 && col >= 1 && col <= 96) {
        const int y = row - 1, x = col - 1;
        const float* b = (ci2 < 64)
            ? &feat[((n * C + 2 * ci2) * H + y) * W + x]
            : &wgt [((n * CW + 2 * (ci2 - 64)) * H + y) * W + x];
        f0 = b[0];
        f1 = b[HW];
    }
    u32 hi, lo;
    split2(f0, f1, hi, lo);
    g_inhi[idx] = hi;
    g_inlo[idx] = lo;
}

// ===========================================================================
// conv1 mma v3: cp.async staging from pre-split inputs, double-buffered input.
// 2 image rows per block; 128 co x 192 px; 512 threads; warp tile 32co x 48px.
// ===========================================================================
constexpr int CISTR = 424;                 // u32 per ci2 (4 rows x 100 + pad); mod 32 == 8
constexpr int IHALF = 24 * CISTR;          // 10176 (HI half of one buffer)
constexpr int IBSZ  = 2 * IHALF;           // 20352 (HI+LO)
constexpr int AB    = 2 * IBSZ;            // 40704
constexpr int ASTR  = 136;                 // mod 32 == 8
constexpr int ATILE = 24 * ASTR;           // 3264
constexpr int SM_U32  = AB + 4 * ATILE;    // 53760
constexpr int SM_BYTES = SM_U32 * 4;       // 215040 B

__global__ __launch_bounds__(512, 1) void k_conv1_mma(
    const float* __restrict__ b1,
    const float* __restrict__ w2,   const float* __restrict__ b2,
    const float* __restrict__ bbuf)
{
    extern __shared__ u32 sm[];
    const int tid  = threadIdx.x;
    const int wid  = tid >> 5;
    const int lane = tid & 31;
    const int wm = wid & 3;
    const int wn = wid >> 2;
    const int r  = lane >> 2;
    const int q  = lane & 3;

    const int n  = blockIdx.z;
    const int y0 = blockIdx.y * 2;

    float d[2][6][4];
    #pragma unroll
    for (int mi = 0; mi < 2; mi++)
        #pragma unroll
        for (int ni = 0; ni < 6; ni++)
            #pragma unroll
            for (int e = 0; e < 4; e++) d[mi][ni][e] = 0.f;

    auto stageA = [&](int tap, int cg, int buf) {
        const u32* srcH = g_w1hi + (tap * 96 + cg * 24) * 128;
        const u32* srcL = g_w1lo + (tap * 96 + cg * 24) * 128;
        u32* dH = sm + AB + buf * 2 * ATILE;
        u32* dL = dH + ATILE;
        #pragma unroll
        for (int it = 0; it < 2; it++) {
            int i = tid + it * 512;
            if (i < 768) {
                int ci2l = i >> 5;
                int c4   = (i & 31) * 4;
                cp16(smem_u32p(&dH[ci2l * ASTR + c4]), &srcH[ci2l * 128 + c4]);
                cp16(smem_u32p(&dL[ci2l * ASTR + c4]), &srcL[ci2l * 128 + c4]);
            }
        }
    };

    // stage ci2 range [c0,c1) of group cgT into buffer buf (rows y0-1..y0+2 = padded y0..y0+3)
    auto stageInRange = [&](int cgT, int buf, int c0, int c1) {
        const int ibase = buf * IBSZ;
        const int cnt = (c1 - c0) * 200;    // per ci2: 2 arrays x 4 rows x 25 float4
        for (int i = tid; i < cnt; i += 512) {
            int ci2o = i / 200;
            int rem  = i - ci2o * 200;
            int arr  = rem / 100;
            int rem2 = rem - arr * 100;
            int rr   = rem2 / 25;
            int f4   = rem2 - rr * 25;
            int dst  = ibase + arr * IHALF + (c0 + ci2o) * CISTR + rr * 100 + f4 * 4;
            int src  = ((n * IN_CI + cgT * 24 + c0 + ci2o) * IN_R + y0 + rr) * IN_CSTR + f4 * 4;
            cp16(smem_u32p(&sm[dst]), arr ? &g_inlo[src] : &g_inhi[src]);
        }
    };

    stageInRange(0, 0, 0, 24);
    stageA(0, 0, 0);
    cp_commit();

    const int prow = wn >> 1;
    const int px0  = (wn & 1) * 48;

    int it = 0;
    for (int cg = 0; cg < 4; cg++) {
        const int ib = (cg & 1) * IBSZ;
        for (int tap = 0; tap < 9; tap++, it++) {
            const int abuf = it & 1;
            __syncthreads();
            if (tap >= 2 && tap <= 5 && cg < 3)
                stageInRange(cg + 1, (cg + 1) & 1, (tap - 2) * 6, (tap - 1) * 6);
            if (it + 1 < 36) {
                stageA((it + 1) % 9, (it + 1) / 9, abuf ^ 1);
                cp_commit();
                cp_wait<1>();
            } else {
                cp_wait<0>();
            }
            __syncthreads();

            const int ky = tap / 3, kx = tap % 3;
            const u32* AH = sm + AB + abuf * 2 * ATILE;
            const u32* AL = AH + ATILE;
            const int boff = (prow + ky) * 100 + kx + px0;

            #pragma unroll
            for (int s = 0; s < 3; s++) {
                const int kb2 = s * 8;
                u32 ahi[2][4], alo[2][4];
                #pragma unroll
                for (int mi = 0; mi < 2; mi++) {
                    const int ra = wm * 32 + mi * 16 + r;
                    ahi[mi][0] = AH[(kb2 + q) * ASTR + ra];
                    ahi[mi][1] = AH[(kb2 + q) * ASTR + ra + 8];
                    ahi[mi][2] = AH[(kb2 + 4 + q) * ASTR + ra];
                    ahi[mi][3] = AH[(kb2 + 4 + q) * ASTR + ra + 8];
                    alo[mi][0] = AL[(kb2 + q) * ASTR + ra];
                    alo[mi][1] = AL[(kb2 + q) * ASTR + ra + 8];
                    alo[mi][2] = AL[(kb2 + 4 + q) * ASTR + ra];
                    alo[mi][3] = AL[(kb2 + 4 + q) * ASTR + ra + 8];
                }
                #pragma unroll
                for (int ni = 0; ni < 6; ni++) {
                    const int a0 = (kb2 + q) * CISTR + boff + ni * 8 + r;
                    const int a1 = (kb2 + 4 + q) * CISTR + boff + ni * 8 + r;
                    const u32 bhi0 = sm[ib + a0];
                    const u32 bhi1 = sm[ib + a1];
                    const u32 blo0 = sm[ib + IHALF + a0];
                    const u32 blo1 = sm[ib + IHALF + a1];
                    #pragma unroll
                    for (int mi = 0; mi < 2; mi++) {
                        mma_bf16(d[mi][ni], ahi[mi], bhi0, bhi1);
                        mma_bf16(d[mi][ni], ahi[mi], blo0, blo1);
                        mma_bf16(d[mi][ni], alo[mi], bhi0, bhi1);
                    }
                }
            }
        }
    }
    __syncthreads();

    // epilogue: hmid = tanh(D + b1) -> sH [co][194]
    float* sH = reinterpret_cast<float*>(sm);
    #pragma unroll
    for (int mi = 0; mi < 2; mi++) {
        const int row = wm * 32 + mi * 16 + r;
        const float bb0 = b1[row];
        const float bb1 = b1[row + 8];
        #pragma unroll
        for (int ni = 0; ni < 6; ni++) {
            const int px = prow * 96 + px0 + ni * 8 + 2 * q;
            sH[row * 194 + px]           = tanhf(d[mi][ni][0] + bb0);
            sH[row * 194 + px + 1]       = tanhf(d[mi][ni][1] + bb0);
            sH[(row + 8) * 194 + px]     = tanhf(d[mi][ni][2] + bb1);
            sH[(row + 8) * 194 + px + 1] = tanhf(d[mi][ni][3] + bb1);
        }
    }
    __syncthreads();

    float* sW2 = reinterpret_cast<float*>(sm) + 24832;
    float* sBv = reinterpret_cast<float*>(sm) + 29440;
    float* sBB = reinterpret_cast<float*>(sm) + 36544;
    #pragma unroll
    for (int itr = 0; itr < 9; itr++) {
        int i = tid + itr * 512;
        int ci = i / 36;
        int ch = i - ci * 36;
        sW2[i] = w2[ch * 128 + ci];
    }
    if (tid < 54) sBB[tid] = bbuf[tid];
    __syncthreads();

    if (tid < 384) {
        const int px  = tid >> 1;
        const int ch0 = (tid & 1) * 18;
        float a2c[18];
        #pragma unroll
        for (int qq = 0; qq < 18; qq++) a2c[qq] = 0.f;
        for (int ci = 0; ci < 128; ci++) {
            const float hv = sH[ci * 194 + px];
            const float* wr = &sW2[ci * 36 + ch0];
            #pragma unroll
            for (int qq = 0; qq < 18; qq++)
                a2c[qq] = fmaf(wr[qq], hv, a2c[qq]);
        }
        #pragma unroll
        for (int qq = 0; qq < 18; qq++)
            sBv[px * 37 + ch0 + qq] = tanhf(a2c[qq] + b2[ch0 + qq]);
    }
    __syncthreads();

    for (int i = tid; i < 54 * 192; i += 512) {
        const int j  = i / 192;
        const int px = i - j * 192;
        const int row = px / 96;
        const int x   = px - row * 96;
        const int m  = j / 9;
        const int l  = j - m * 9;
        float s = 0.f;
        #pragma unroll
        for (int t = 0; t < 6; t++)
            s = fmaf(sBv[px * 37 + m * 6 + t], sBB[t * 9 + l], s);
        g_bases[(n * 54 + j) * HW + (y0 + row) * W + x] = s;
    }
}

// ===========================================================================
// V-GEMM via mma.sync bf16, staging from pre-split arrays via cp.async.
// ===========================================================================
constexpr int PAD = 68;
constexpr int VG_SMEM = 4 * 128 * PAD * 4;

__global__ __launch_bounds__(512, 1) void k_vgemm_mma()
{
    extern __shared__ u32 vsm[];
    u32* sAhi = vsm;
    u32* sAlo = vsm + 128 * PAD;
    u32* sBhi = vsm + 2 * 128 * PAD;
    u32* sBlo = vsm + 3 * 128 * PAD;

    const int tid = threadIdx.x;
    const int n  = blockIdx.z;
    const int r0 = blockIdx.y * 128;
    const int p0 = blockIdx.x * 128;

    // A: contiguous cp16
    #pragma unroll
    for (int it = 0; it < 4; it++) {
        int i = tid + it * 512;        // < 2048
        int m  = i >> 4;
        int k4 = i & 15;
        cp16(smem_u32p(&sAhi[m * PAD + k4 * 4]), &g_ahi[(r0 + m) * 64 + k4 * 4]);
        cp16(smem_u32p(&sAlo[m * PAD + k4 * 4]), &g_alo[(r0 + m) * 64 + k4 * 4]);
    }
    // B: transposed cp4 from padded split arrays (feat channels = ci2 < 64)
    #pragma unroll
    for (int it = 0; it < 16; it++) {
        int idx = tid + it * 512;
        int k2 = idx >> 7;
        int p  = idx & 127;
        int gp = p0 + p;
        int row = gp / 96;
        int col = gp - row * 96;
        int src = ((n * IN_CI + k2) * IN_R + row + 1) * IN_CSTR + col + 1;
        cp4(smem_u32p(&sBhi[p * PAD + k2]), &g_inhi[src]);
        cp4(smem_u32p(&sBlo[p * PAD + k2]), &g_inlo[src]);
    }
    cp_commit();
    cp_wait<0>();
    __syncthreads();

    const int wid = tid >> 5;
    const int lane = tid & 31;
    const int wm = wid & 3;
    const int wn = wid >> 2;
    const int r  = lane >> 2;
    const int q  = lane & 3;

    float d[2][4][4];
    #pragma unroll
    for (int mi = 0; mi < 2; mi++)
        #pragma unroll
        for (int ni = 0; ni < 4; ni++)
            #pragma unroll
            for (int e = 0; e < 4; e++) d[mi][ni][e] = 0.f;

    #pragma unroll
    for (int ks = 0; ks < 8; ks++) {
        const int kc = ks * 8;
        u32 ahi[2][4], alo[2][4];
        #pragma unroll
        for (int mi = 0; mi < 2; mi++) {
            const int ra = wm * 32 + mi * 16 + r;
            ahi[mi][0] = sAhi[ra * PAD + kc + q];
            ahi[mi][1] = sAhi[(ra + 8) * PAD + kc + q];
            ahi[mi][2] = sAhi[ra * PAD + kc + 4 + q];
            ahi[mi][3] = sAhi[(ra + 8) * PAD + kc + 4 + q];
            alo[mi][0] = sAlo[ra * PAD + kc + q];
            alo[mi][1] = sAlo[(ra + 8) * PAD + kc + q];
            alo[mi][2] = sAlo[ra * PAD + kc + 4 + q];
            alo[mi][3] = sAlo[(ra + 8) * PAD + kc + 4 + q];
        }
        #pragma unroll
        for (int ni = 0; ni < 4; ni++) {
            const int nb = wn * 32 + ni * 8 + r;
            u32 bhi0 = sBhi[nb * PAD + kc + q];
            u32 bhi1 = sBhi[nb * PAD + kc + 4 + q];
            u32 blo0 = sBlo[nb * PAD + kc + q];
            u32 blo1 = sBlo[nb * PAD + kc + 4 + q];
            #pragma unroll
            for (int mi = 0; mi < 2; mi++) {
                mma_bf16(d[mi][ni], ahi[mi], bhi0, bhi1);
                mma_bf16(d[mi][ni], ahi[mi], blo0, blo1);
                mma_bf16(d[mi][ni], alo[mi], bhi0, bhi1);
            }
        }
    }

    float* Vn = g_v + (size_t)n * K768 * HW;
    #pragma unroll
    for (int mi = 0; mi < 2; mi++) {
        const int row = r0 + wm * 32 + mi * 16 + r;
        #pragma unroll
        for (int ni = 0; ni < 4; ni++) {
            const int col = p0 + wn * 32 + ni * 8 + 2 * q;
            *reinterpret_cast<float2*>(&Vn[(size_t)row * HW + col]) =
                make_float2(d[mi][ni][0], d[mi][ni][1]);
            *reinterpret_cast<float2*>(&Vn[(size_t)(row + 8) * HW + col]) =
                make_float2(d[mi][ni][2], d[mi][ni][3]);
        }
    }
}

// ===========================================================================
// combine: m-outer loop, 16 channels per block.
// ===========================================================================
__global__ __launch_bounds__(256) void k_combine(
    const float* __restrict__ bias, float* __restrict__ out)
{
    const int p  = blockIdx.x * 256 + threadIdx.x;
    const int cb = blockIdx.y * 16;
    const int n  = p / HW;
    const int hw = p - n * HW;
    const int y  = hw / W;
    const int x  = hw - y * W;

    int  off[9];
    u32  okm = 0;
    #pragma unroll
    for (int l = 0; l < 9; l++) {
        const int dy = l / 3 - 1, dx = l % 3 - 1;
        const bool ok = (unsigned)(y + dy) < (unsigned)H && (unsigned)(x + dx) < (unsigned)W;
        off[l] = ok ? (dy * W + dx) : 0;
        okm |= (ok ? 1u : 0u) << l;
    }

    float acc[16];
    #pragma unroll
    for (int ci = 0; ci < 16; ci++) acc[ci] = 0.f;

    const float* Vn = g_v + (size_t)n * K768 * HW + hw;

    #pragma unroll
    for (int m = 0; m < 6; m++) {
        float bs[9];
        #pragma unroll
        for (int l = 0; l < 9; l++) {
            float t = __ldg(&g_bases[(n * 54 + m * 9 + l) * HW + hw]);
            bs[l] = (okm >> l & 1u) ? t : 0.f;
        }
        const float* Vm = Vn + (size_t)(cb * 6 + m) * HW;
        #pragma unroll
        for (int ci = 0; ci < 16; ci++) {
            const float* row = Vm + (size_t)(ci * 6) * HW;
            float s = 0.f;
            #pragma unroll
            for (int l = 0; l < 9; l++)
                s = fmaf(bs[l], __ldg(row + off[l]), s);
            acc[ci] += s;
        }
    }

    float* on = out + (size_t)n * C * HW + hw;
    #pragma unroll
    for (int ci = 0; ci < 16; ci++)
        on[(size_t)(cb + ci) * HW] = acc[ci] + __ldg(&bias[cb + ci]);
}

// ---------------------------------------------------------------------------
extern "C" void kernel_launch(void* const* d_in, const int* in_sizes, int n_in,
                              void* d_out, int out_size)
{
    const float* feat = (const float*)d_in[0];
    const float* wgt  = (const float*)d_in[1];
    const float* w1   = (const float*)d_in[2];
    const float* b1   = (const float*)d_in[3];
    const float* w2   = (const float*)d_in[4];
    const float* b2   = (const float*)d_in[5];
    const float* bbuf = (const float*)d_in[6];
    const float* coef = (const float*)d_in[7];
    const float* bias = (const float*)d_in[8];
    float* out = (float*)d_out;

    static bool attr_set = false;
    if (!attr_set) {
        cudaFuncSetAttribute(k_conv1_mma,
                             cudaFuncAttributeMaxDynamicSharedMemorySize, SM_BYTES);
        cudaFuncSetAttribute(k_vgemm_mma,
                             cudaFuncAttributeMaxDynamicSharedMemorySize, VG_SMEM);
        attr_set = true;
    }

    k_prep_in<<<(N * IN_NSTR) / 512, 512>>>(feat, wgt);
    k_prep_w1<<<(9 * 96 * 128) / 512, 512>>>(w1);
    k_prep_a<<<(K768 * 64) / 256, 256>>>(coef);

    dim3 g1(1, H / 2, N);
    k_conv1_mma<<<g1, 512, SM_BYTES>>>(b1, w2, b2, bbuf);

    dim3 g3(HW / 128, K768 / 128, N);
    k_vgemm_mma<<<g3, 512, VG_SMEM>>>();

    dim3 g4((N * HW) / 256, 8);
    k_combine<<<g4, 256>>>(bias, out);
}